// round 7
// baseline (speedup 1.0000x reference)
#include <cuda_runtime.h>
#include <cuda_fp16.h>
#include <cstdint>
#include <cstddef>

// ---------------------------------------------------------------------------
// SelfAttention on sm_103, mma.sync fp16 x3 with MIXED accumulate:
//   x = h + l (fp16 hi/lo, 22-bit effective mantissa)
//   A*B ~= Ah*Bh (f32 acc, exact products) + Al*Bh + Ah*Bl (f16 acc)
// Rationale: tensor pipe pinned at ~49% "util" across R4-R6 => fp32-acc HMMA
// is half-rate; f16-acc correction terms may run full rate => 1.5x on all
// tensor work. Corrections are ~2^-11 of main; f16 accumulation error is
// negligible (folded into f32 mains per k-tile / at epilogue).
// ---------------------------------------------------------------------------

#define Tn     2048
#define Cn     2048
#define QKVW   3072          // (16 + 2*4) * 128
#define ROWS   4096          // B*T
#define GK     2048          // K dim of both big GEMMs

typedef __half f16;

__device__ __align__(16) float g_qkv[(size_t)ROWS * QKVW];
__device__ __align__(16) f16  g_xh[(size_t)ROWS * GK];
__device__ __align__(16) f16  g_xl[(size_t)ROWS * GK];
__device__ __align__(16) f16  g_wah[(size_t)QKVW * GK];
__device__ __align__(16) f16  g_wal[(size_t)QKVW * GK];
__device__ __align__(16) f16  g_wph[(size_t)Cn * GK];
__device__ __align__(16) f16  g_wpl[(size_t)Cn * GK];
__device__ __align__(16) f16  g_qh[(size_t)2 * 16 * Tn * 128];
__device__ __align__(16) f16  g_ql[(size_t)2 * 16 * Tn * 128];
__device__ __align__(16) f16  g_kh[(size_t)2 * 4 * Tn * 128];
__device__ __align__(16) f16  g_kl[(size_t)2 * 4 * Tn * 128];
__device__ __align__(16) f16  g_vth[(size_t)2 * 4 * 128 * Tn];
__device__ __align__(16) f16  g_vtl[(size_t)2 * 4 * 128 * Tn];
__device__ __align__(16) f16  g_yh[(size_t)ROWS * Cn];
__device__ __align__(16) f16  g_yl[(size_t)ROWS * Cn];

// 1/sqrt(128) * log2(e): softmax scale + exp->exp2, folded into q
#define QK_SCALE (0.08838834764831845f * 1.4426950408889634f)

// ============================ helpers =======================================
__device__ __forceinline__ float ex2f(float x) {
    float r;
    asm("ex2.approx.ftz.f32 %0, %1;" : "=f"(r) : "f"(x));
    return r;
}
// pack two fp32 -> f16x2 reg; first arg goes to bits [15:0]
__device__ __forceinline__ uint32_t pkh2(float lo, float hi) {
    __half2 h = __floats2half2_rn(lo, hi);
    return *reinterpret_cast<uint32_t*>(&h);
}
__device__ __forceinline__ float2 uph2(uint32_t u) {
    __half2 h = *reinterpret_cast<__half2*>(&u);
    return __half22float2(h);
}
// main term: f16 inputs, f32 accumulate
__device__ __forceinline__ void mma_f32a(float (&d)[4], const uint32_t (&a)[4],
                                         const uint32_t* b) {
    asm volatile(
        "mma.sync.aligned.m16n8k16.row.col.f32.f16.f16.f32 "
        "{%0,%1,%2,%3}, {%4,%5,%6,%7}, {%8,%9}, {%0,%1,%2,%3};"
        : "+f"(d[0]), "+f"(d[1]), "+f"(d[2]), "+f"(d[3])
        : "r"(a[0]), "r"(a[1]), "r"(a[2]), "r"(a[3]), "r"(b[0]), "r"(b[1]));
}
// correction term: f16 inputs, f16 accumulate
__device__ __forceinline__ void mma_f16a(uint32_t (&d)[2], const uint32_t (&a)[4],
                                         const uint32_t* b) {
    asm volatile(
        "mma.sync.aligned.m16n8k16.row.col.f16.f16.f16.f16 "
        "{%0,%1}, {%2,%3,%4,%5}, {%6,%7}, {%0,%1};"
        : "+r"(d[0]), "+r"(d[1])
        : "r"(a[0]), "r"(a[1]), "r"(a[2]), "r"(a[3]), "r"(b[0]), "r"(b[1]));
}
__device__ __forceinline__ void ldsm4(uint32_t* r, uint32_t a) {
    asm volatile("ldmatrix.sync.aligned.m8n8.x4.shared.b16 {%0,%1,%2,%3}, [%4];"
                 : "=r"(r[0]), "=r"(r[1]), "=r"(r[2]), "=r"(r[3]) : "r"(a));
}
__device__ __forceinline__ uint32_t smem_u32(const void* p) {
    uint32_t a;
    asm("{ .reg .u64 t; cvta.to.shared.u64 t, %1; cvt.u32.u64 %0, t; }"
        : "=r"(a) : "l"(p));
    return a;
}
#define CP16(dst, src) \
    asm volatile("cp.async.cg.shared.global [%0], [%1], 16;" \
                 :: "r"(dst), "l"(src) : "memory")
#define CPCOMMIT() asm volatile("cp.async.commit_group;" ::: "memory")
#define CPWAIT1()  asm volatile("cp.async.wait_group 1;" ::: "memory")
#define CPWAIT0()  asm volatile("cp.async.wait_group 0;" ::: "memory")

// ---------------------------------------------------------------------------
// split x -> f16 hi/lo
// ---------------------------------------------------------------------------
__global__ __launch_bounds__(256) void splitx_kernel(const float* __restrict__ x) {
    size_t i = ((size_t)blockIdx.x * 256 + threadIdx.x) * 4;
    float4 v = *(const float4*)(x + i);
    f16 h0 = __float2half_rn(v.x), h1 = __float2half_rn(v.y);
    f16 h2 = __float2half_rn(v.z), h3 = __float2half_rn(v.w);
    f16 l0 = __float2half_rn(v.x - __half2float(h0));
    f16 l1 = __float2half_rn(v.y - __half2float(h1));
    f16 l2 = __float2half_rn(v.z - __half2float(h2));
    f16 l3 = __float2half_rn(v.w - __half2float(h3));
    g_xh[i] = h0; g_xh[i + 1] = h1; g_xh[i + 2] = h2; g_xh[i + 3] = h3;
    g_xl[i] = l0; g_xl[i + 1] = l1; g_xl[i + 2] = l2; g_xl[i + 3] = l3;
}

// ---------------------------------------------------------------------------
// transpose + split weights: in [2048][Ccols] fp32 -> hi/lo [Ccols][2048] f16
// ---------------------------------------------------------------------------
__global__ __launch_bounds__(256) void wsplit_kernel(
    const float* __restrict__ in, f16* __restrict__ hi, f16* __restrict__ lo,
    int Ccols)
{
    __shared__ float tb[32][33];
    const int bx = blockIdx.x * 32, by = blockIdx.y * 32;
    const int tx = threadIdx.x, ty = threadIdx.y;
#pragma unroll
    for (int j = 0; j < 32; j += 8)
        tb[ty + j][tx] = in[(size_t)(by + ty + j) * Ccols + bx + tx];
    __syncthreads();
#pragma unroll
    for (int j = 0; j < 32; j += 8) {
        float v = tb[tx][ty + j];
        size_t o = (size_t)(bx + ty + j) * GK + by + tx;
        f16 h = __float2half_rn(v);
        hi[o] = h;
        lo[o] = __float2half_rn(v - __half2float(h));
    }
}

// ---------------------------------------------------------------------------
// fp16x3 mixed-acc GEMM: C[M,N] = A[M,2048] @ BT[N,2048]^T.
// CTA tile 64x128, kchunk 32, cp.async double buffer, 8 warps (2m x 4n),
// warp tile 32x32. smem stage: Ah@0(5120) Al@5120 Bh@10240(10240) Bl@20480.
// ---------------------------------------------------------------------------
#define GS_STAGE 30720
#define GSM (2 * GS_STAGE)

__global__ __launch_bounds__(256, 2) void hgemm3_kernel(
    const f16* __restrict__ Ah, const f16* __restrict__ Al,
    const f16* __restrict__ Bh, const f16* __restrict__ Bl,
    float* __restrict__ C, int N)
{
    extern __shared__ char sm[];
    const uint32_t sb = smem_u32(sm);
    const int tid = threadIdx.x;
    const int lane = tid & 31, wid = tid >> 5;
    const int lg = lane >> 2, tq = lane & 3;
    const int mi = wid & 1, ni = wid >> 1;
    const size_t m0 = (size_t)blockIdx.y * 64, n0 = (size_t)blockIdx.x * 128;

    const uint32_t abase =
        (uint32_t)((mi * 32 + (lane & 15)) * 80 + (lane >> 4) * 16);
    const uint32_t bbase =
        (uint32_t)(10240 + (ni * 32 + (lane & 7) + ((lane >> 4) * 8)) * 80 +
                   ((lane >> 3) & 1) * 16);

    // loaders: A 1 vec/thread/array, B 2 vecs/thread/array
    const int ar = tid >> 2;
    const int ac = tid & 3;
    const f16* pAh = Ah + (m0 + ar) * GK + ac * 8;
    const f16* pAl = Al + (m0 + ar) * GK + ac * 8;
    const f16* pBh = Bh + (n0 + ar) * GK + ac * 8;
    const f16* pBl = Bl + (n0 + ar) * GK + ac * 8;
    const uint32_t sdA = sb + ar * 80 + ac * 16;
    const uint32_t sdB = sb + 10240 + ar * 80 + ac * 16;

    float c[2][4][4];
    uint32_t cc[2][4][2];
#pragma unroll
    for (int a = 0; a < 2; a++)
#pragma unroll
        for (int b = 0; b < 4; b++) {
#pragma unroll
            for (int d = 0; d < 4; d++) c[a][b][d] = 0.f;
            cc[a][b][0] = 0u; cc[a][b][1] = 0u;
        }

    // stage 0
    {
        CP16(sdA,         pAh);
        CP16(sdA + 5120,  pAl);
        CP16(sdB,              pBh);
        CP16(sdB + 64 * 80,    pBh + (size_t)64 * GK);
        CP16(sdB + 10240,           pBl);
        CP16(sdB + 10240 + 64 * 80, pBl + (size_t)64 * GK);
        CPCOMMIT();
    }

#pragma unroll 1
    for (int kt = 0; kt < GK / 32; kt++) {
        const int s = kt & 1;
        if (kt + 1 < GK / 32) {
            uint32_t dA = sdA + (s ^ 1) * GS_STAGE;
            uint32_t dB = sdB + (s ^ 1) * GS_STAGE;
            size_t off = (size_t)(kt + 1) * 32;
            CP16(dA,         pAh + off);
            CP16(dA + 5120,  pAl + off);
            CP16(dB,              pBh + off);
            CP16(dB + 64 * 80,    pBh + off + (size_t)64 * GK);
            CP16(dB + 10240,           pBl + off);
            CP16(dB + 10240 + 64 * 80, pBl + off + (size_t)64 * GK);
            CPCOMMIT();
            CPWAIT1();
        } else {
            CPWAIT0();
        }
        __syncthreads();

        const uint32_t stg = sb + s * GS_STAGE;
#pragma unroll
        for (int kk = 0; kk < 2; kk++) {
            uint32_t ah[2][4], al[2][4];
#pragma unroll
            for (int mt = 0; mt < 2; mt++) {
                uint32_t aa = stg + abase + mt * (16 * 80) + kk * 32;
                ldsm4(ah[mt], aa);
                ldsm4(al[mt], aa + 5120);
            }
            uint32_t bb[4][2];
#pragma unroll
            for (int p = 0; p < 2; p++)
                ldsm4(&bb[2 * p][0], stg + bbase + p * (16 * 80) + kk * 32);
            // main (f32 acc): ah*bh
#pragma unroll
            for (int mt = 0; mt < 2; mt++)
#pragma unroll
                for (int nt = 0; nt < 4; nt++) mma_f32a(c[mt][nt], ah[mt], bb[nt]);
            // corr (f16 acc): al*bh
#pragma unroll
            for (int mt = 0; mt < 2; mt++)
#pragma unroll
                for (int nt = 0; nt < 4; nt++) mma_f16a(cc[mt][nt], al[mt], bb[nt]);
            // reload with B_lo
#pragma unroll
            for (int p = 0; p < 2; p++)
                ldsm4(&bb[2 * p][0], stg + bbase + 10240 + p * (16 * 80) + kk * 32);
            // corr (f16 acc): ah*bl
#pragma unroll
            for (int mt = 0; mt < 2; mt++)
#pragma unroll
                for (int nt = 0; nt < 4; nt++) mma_f16a(cc[mt][nt], ah[mt], bb[nt]);
        }
        __syncthreads();
    }

#pragma unroll
    for (int mt = 0; mt < 2; mt++) {
        size_t r0 = m0 + mi * 32 + mt * 16 + lg;
#pragma unroll
        for (int nt = 0; nt < 4; nt++) {
            float2 f0 = uph2(cc[mt][nt][0]);
            float2 f1 = uph2(cc[mt][nt][1]);
            size_t col = n0 + ni * 32 + nt * 8 + tq * 2;
            *(float2*)(C + r0 * N + col) =
                make_float2(c[mt][nt][0] + f0.x, c[mt][nt][1] + f0.y);
            *(float2*)(C + (r0 + 8) * N + col) =
                make_float2(c[mt][nt][2] + f1.x, c[mt][nt][3] + f1.y);
        }
    }
}

// ---------------------------------------------------------------------------
// RoPE + f16 split: q (slots 0-3, scaled) -> g_qh/ql; k (slot 4) -> g_kh/kl
// ---------------------------------------------------------------------------
__global__ __launch_bounds__(256) void rope_split_kernel(
    const float* __restrict__ cosb, const float* __restrict__ sinb)
{
    int idx = blockIdx.x * 256 + threadIdx.x;     // ROWS*4*5*64
    int d = idx & 63;
    int rg = idx >> 6;
    int slot = rg % 5;
    int q5 = rg / 5;
    int grp = q5 & 3;
    int row = q5 >> 2;
    int b = row >> 11, t = row & (Tn - 1);

    const float* p = g_qkv + (size_t)row * QKVW + grp * 768 + slot * 128 + d;
    float x1 = p[0], x2 = p[64];
    float cc = cosb[t * 64 + d], ss = sinb[t * 64 + d];
    float o1 = x1 * cc - x2 * ss;
    float o2 = x1 * ss + x2 * cc;

    f16 *dh, *dl;
    size_t base;
    if (slot < 4) {
        o1 *= QK_SCALE; o2 *= QK_SCALE;
        int head = grp * 4 + slot;
        base = ((size_t)(b * 16 + head) * Tn + t) * 128 + d;
        dh = g_qh; dl = g_ql;
    } else {
        base = ((size_t)(b * 4 + grp) * Tn + t) * 128 + d;
        dh = g_kh; dl = g_kl;
    }
    f16 h1 = __float2half_rn(o1), h2 = __float2half_rn(o2);
    dh[base]      = h1;
    dh[base + 64] = h2;
    dl[base]      = __float2half_rn(o1 - __half2float(h1));
    dl[base + 64] = __float2half_rn(o2 - __half2float(h2));
}

// ---------------------------------------------------------------------------
// v: split + transpose -> g_vth/vtl [b][g][d][t]
// ---------------------------------------------------------------------------
__global__ __launch_bounds__(256) void vsplit_kernel() {
    __shared__ float tb[32][33];
    const int bg = blockIdx.z;
    const int t0 = blockIdx.x * 32, d0 = blockIdx.y * 32;
    const int tx = threadIdx.x, ty = threadIdx.y;
    const int b = bg >> 2, grp = bg & 3;
#pragma unroll
    for (int j = 0; j < 32; j += 8)
        tb[ty + j][tx] = g_qkv[((size_t)b * Tn + t0 + ty + j) * QKVW +
                               grp * 768 + 640 + d0 + tx];
    __syncthreads();
#pragma unroll
    for (int j = 0; j < 32; j += 8) {
        float v = tb[tx][ty + j];
        size_t o = ((size_t)bg * 128 + d0 + ty + j) * Tn + t0 + tx;
        f16 h = __float2half_rn(v);
        g_vth[o] = h;
        g_vtl[o] = __float2half_rn(v - __half2float(h));
    }
}

// ---------------------------------------------------------------------------
// Flash attention, fp16x3 mixed accumulate.
// CTA = (qb, h, b): 128 q rows, 8 warps x m16. Key tiles of 64.
// smem: Qh/Ql [128 rows x 272B], Kh/Kl [64 x 272B], Vth/Vtl [128 d x 144B].
// ---------------------------------------------------------------------------
#define AQ_H 0
#define AQ_L 34816
#define AK_H 69632
#define AK_L 87040
#define AV_H 104448
#define AV_L 122880
#define ATT_SMEM 141312

__global__ __launch_bounds__(256, 1) void attn_kernel() {
    extern __shared__ char sm[];
    const uint32_t sb = smem_u32(sm);
    const int tid = threadIdx.x;
    const int lane = tid & 31, wid = tid >> 5;
    const int lg = lane >> 2, tq = lane & 3;
    const int qb = blockIdx.x, h = blockIdx.y, b = blockIdx.z;
    const int grp = h >> 2;

    const uint32_t qbase = sb + AQ_H + (wid * 16 + (lane & 15)) * 272 +
                           (lane >> 4) * 16;
    const uint32_t kbase = sb + AK_H + ((lane & 7) + ((lane >> 4) * 8)) * 272 +
                           ((lane >> 3) & 1) * 16;
    const uint32_t vbase = sb + AV_H + ((lane & 7) + ((lane >> 4) * 8)) * 144 +
                           ((lane >> 3) & 1) * 16;

    // load Q (hi/lo), 128 x 128 f16 each
    {
        const f16* qhp = g_qh + ((size_t)(b * 16 + h) * Tn + qb * 128) * 128;
        const f16* qlp = g_ql + ((size_t)(b * 16 + h) * Tn + qb * 128) * 128;
#pragma unroll
        for (int it = 0; it < 8; it++) {
            int idx = it * 256 + tid;
            int r = idx >> 4, hx = idx & 15;
            *(uint4*)(sm + AQ_H + r * 272 + hx * 16) = *(const uint4*)(qhp + (size_t)r * 128 + hx * 8);
            *(uint4*)(sm + AQ_L + r * 272 + hx * 16) = *(const uint4*)(qlp + (size_t)r * 128 + hx * 8);
        }
    }

    float o[16][4];
#pragma unroll
    for (int i = 0; i < 16; i++)
#pragma unroll
        for (int j = 0; j < 4; j++) o[i][j] = 0.f;
    float m0 = __int_as_float(0xff800000), m1 = m0;
    float l0 = 0.f, l1 = 0.f;

    const f16* khp = g_kh + (size_t)(b * 4 + grp) * Tn * 128;
    const f16* klp = g_kl + (size_t)(b * 4 + grp) * Tn * 128;
    const f16* vhp = g_vth + (size_t)(b * 4 + grp) * 128 * Tn;
    const f16* vlp = g_vtl + (size_t)(b * 4 + grp) * 128 * Tn;

#pragma unroll 1
    for (int kt = 0; kt < Tn / 64; kt++) {
        __syncthreads();
#pragma unroll
        for (int it = 0; it < 4; it++) {
            int idx = it * 256 + tid;
            int r = idx >> 4, hx = idx & 15;
            size_t go = ((size_t)kt * 64 + r) * 128 + hx * 8;
            *(uint4*)(sm + AK_H + r * 272 + hx * 16) = *(const uint4*)(khp + go);
            *(uint4*)(sm + AK_L + r * 272 + hx * 16) = *(const uint4*)(klp + go);
        }
#pragma unroll
        for (int it = 0; it < 4; it++) {
            int idx = it * 256 + tid;
            int r = idx >> 3, hx = idx & 7;
            size_t go = (size_t)r * Tn + kt * 64 + hx * 8;
            *(uint4*)(sm + AV_H + r * 144 + hx * 16) = *(const uint4*)(vhp + go);
            *(uint4*)(sm + AV_L + r * 144 + hx * 16) = *(const uint4*)(vlp + go);
        }
        __syncthreads();

        // ---- S = Q K^T: main f32 acc, corrections f16 acc ----
        float s[8][4];
        uint32_t scorr[8][2];
#pragma unroll
        for (int i = 0; i < 8; i++) {
#pragma unroll
            for (int j = 0; j < 4; j++) s[i][j] = 0.f;
            scorr[i][0] = 0u; scorr[i][1] = 0u;
        }

#pragma unroll
        for (int kk = 0; kk < 8; kk++) {
            uint32_t qah[4], qal[4];
            ldsm4(qah, qbase + kk * 32);
            ldsm4(qal, qbase + (AQ_L - AQ_H) + kk * 32);
            uint32_t kb[8][2];
#pragma unroll
            for (int p = 0; p < 4; p++)
                ldsm4(&kb[2 * p][0], kbase + p * (16 * 272) + kk * 32);
#pragma unroll
            for (int nt = 0; nt < 8; nt++) mma_f32a(s[nt], qah, kb[nt]);
#pragma unroll
            for (int nt = 0; nt < 8; nt++) mma_f16a(scorr[nt], qal, kb[nt]);
#pragma unroll
            for (int p = 0; p < 4; p++)
                ldsm4(&kb[2 * p][0], kbase + (AK_L - AK_H) + p * (16 * 272) + kk * 32);
#pragma unroll
            for (int nt = 0; nt < 8; nt++) mma_f16a(scorr[nt], qah, kb[nt]);
        }
        // fold corrections
#pragma unroll
        for (int nt = 0; nt < 8; nt++) {
            float2 f0 = uph2(scorr[nt][0]);
            float2 f1 = uph2(scorr[nt][1]);
            s[nt][0] += f0.x; s[nt][1] += f0.y;
            s[nt][2] += f1.x; s[nt][3] += f1.y;
        }

        // ---- online softmax (2 rows per lane: lg, lg+8) ----
        float mx0 = s[0][0], mx1 = s[0][2];
#pragma unroll
        for (int nt = 0; nt < 8; nt++) {
            mx0 = fmaxf(mx0, fmaxf(s[nt][0], s[nt][1]));
            mx1 = fmaxf(mx1, fmaxf(s[nt][2], s[nt][3]));
        }
        mx0 = fmaxf(mx0, __shfl_xor_sync(0xffffffffu, mx0, 1));
        mx0 = fmaxf(mx0, __shfl_xor_sync(0xffffffffu, mx0, 2));
        mx1 = fmaxf(mx1, __shfl_xor_sync(0xffffffffu, mx1, 1));
        mx1 = fmaxf(mx1, __shfl_xor_sync(0xffffffffu, mx1, 2));
        float mn0 = fmaxf(m0, mx0), mn1 = fmaxf(m1, mx1);
        float cr0 = ex2f(m0 - mn0), cr1 = ex2f(m1 - mn1);
        m0 = mn0; m1 = mn1;
        float sum0 = 0.f, sum1 = 0.f;
#pragma unroll
        for (int nt = 0; nt < 8; nt++) {
            s[nt][0] = ex2f(s[nt][0] - mn0);
            s[nt][1] = ex2f(s[nt][1] - mn0);
            s[nt][2] = ex2f(s[nt][2] - mn1);
            s[nt][3] = ex2f(s[nt][3] - mn1);
            sum0 += s[nt][0] + s[nt][1];
            sum1 += s[nt][2] + s[nt][3];
        }
        sum0 += __shfl_xor_sync(0xffffffffu, sum0, 1);
        sum0 += __shfl_xor_sync(0xffffffffu, sum0, 2);
        sum1 += __shfl_xor_sync(0xffffffffu, sum1, 1);
        sum1 += __shfl_xor_sync(0xffffffffu, sum1, 2);
        l0 = l0 * cr0 + sum0;
        l1 = l1 * cr1 + sum1;
#pragma unroll
        for (int nt = 0; nt < 16; nt++) {
            o[nt][0] *= cr0; o[nt][1] *= cr0;
            o[nt][2] *= cr1; o[nt][3] *= cr1;
        }

        // ---- O += P V: main f32 acc, corrections f16 acc ----
        uint32_t ocorr[16][2];
#pragma unroll
        for (int i = 0; i < 16; i++) { ocorr[i][0] = 0u; ocorr[i][1] = 0u; }

#pragma unroll
        for (int kk = 0; kk < 4; kk++) {
            uint32_t ph[4], pl[4];
#pragma unroll
            for (int q2 = 0; q2 < 2; q2++) {
                float e0 = s[2 * kk + q2][0], e1 = s[2 * kk + q2][1];
                ph[2 * q2] = pkh2(e0, e1);
                float2 hp = uph2(ph[2 * q2]);
                pl[2 * q2] = pkh2(e0 - hp.x, e1 - hp.y);
                e0 = s[2 * kk + q2][2]; e1 = s[2 * kk + q2][3];
                ph[2 * q2 + 1] = pkh2(e0, e1);
                hp = uph2(ph[2 * q2 + 1]);
                pl[2 * q2 + 1] = pkh2(e0 - hp.x, e1 - hp.y);
            }
            // A-frag order is a0=r(lg,c2tq) a1=r(lg+8) a2=c+... wait: layout
            // {a0,a1,a2,a3} = {(lg,2tq),(lg+8,2tq),(lg,2tq+8?)}: use same
            // convention as R4-R6 (passed): a[0]=s[2kk][01], a[1]=s[2kk][23],
            // a[2]=s[2kk+1][01], a[3]=s[2kk+1][23].
#pragma unroll
            for (int blk = 0; blk < 2; blk++) {
                uint32_t vb[8][2];
#pragma unroll
                for (int p = 0; p < 4; p++)
                    ldsm4(&vb[2 * p][0], vbase + (blk * 64 + p * 16) * 144 + kk * 32);
#pragma unroll
                for (int j = 0; j < 8; j++) mma_f32a(o[blk * 8 + j], ph, vb[j]);
#pragma unroll
                for (int j = 0; j < 8; j++) mma_f16a(ocorr[blk * 8 + j], pl, vb[j]);
#pragma unroll
                for (int p = 0; p < 4; p++)
                    ldsm4(&vb[2 * p][0], vbase + (AV_L - AV_H) +
                                          (blk * 64 + p * 16) * 144 + kk * 32);
#pragma unroll
                for (int j = 0; j < 8; j++) mma_f16a(ocorr[blk * 8 + j], ph, vb[j]);
            }
        }
        // fold PV corrections
#pragma unroll
        for (int j = 0; j < 16; j++) {
            float2 f0 = uph2(ocorr[j][0]);
            float2 f1 = uph2(ocorr[j][1]);
            o[j][0] += f0.x; o[j][1] += f0.y;
            o[j][2] += f1.x; o[j][3] += f1.y;
        }
    }

    // ---- epilogue: y = O / l, split to f16 hi/lo ----
    float i0 = 1.f / l0, i1 = 1.f / l1;
    size_t row0 = (size_t)b * Tn + qb * 128 + wid * 16 + lg;
#pragma unroll
    for (int nt = 0; nt < 16; nt++) {
        int col = h * 128 + nt * 8 + tq * 2;
        float v0 = o[nt][0] * i0, v1 = o[nt][1] * i0;
        uint32_t hh = pkh2(v0, v1);
        float2 hp = uph2(hh);
        *(uint32_t*)(g_yh + row0 * Cn + col) = hh;
        *(uint32_t*)(g_yl + row0 * Cn + col) = pkh2(v0 - hp.x, v1 - hp.y);
        v0 = o[nt][2] * i1; v1 = o[nt][3] * i1;
        hh = pkh2(v0, v1);
        hp = uph2(hh);
        *(uint32_t*)(g_yh + (row0 + 8) * Cn + col) = hh;
        *(uint32_t*)(g_yl + (row0 + 8) * Cn + col) = pkh2(v0 - hp.x, v1 - hp.y);
    }
}

// ---------------------------------------------------------------------------
extern "C" void kernel_launch(void* const* d_in, const int* in_sizes, int n_in,
                              void* d_out, int out_size) {
    const float* x      = (const float*)d_in[0];
    const float* cosb   = (const float*)d_in[1];
    const float* sinb   = (const float*)d_in[2];
    const float* w_attn = (const float*)d_in[3];
    const float* w_proj = (const float*)d_in[4];
    float* out = (float*)d_out;
    (void)in_sizes; (void)n_in; (void)out_size;

    (void)cudaFuncSetAttribute(hgemm3_kernel,
                               cudaFuncAttributeMaxDynamicSharedMemorySize, GSM);
    (void)cudaFuncSetAttribute(attn_kernel,
                               cudaFuncAttributeMaxDynamicSharedMemorySize, ATT_SMEM);

    float* qkvp = nullptr;
    f16 *xh, *xl, *wah, *wal, *wph, *wpl, *yh, *yl;
    (void)cudaGetSymbolAddress((void**)&qkvp, g_qkv);
    (void)cudaGetSymbolAddress((void**)&xh, g_xh);
    (void)cudaGetSymbolAddress((void**)&xl, g_xl);
    (void)cudaGetSymbolAddress((void**)&wah, g_wah);
    (void)cudaGetSymbolAddress((void**)&wal, g_wal);
    (void)cudaGetSymbolAddress((void**)&wph, g_wph);
    (void)cudaGetSymbolAddress((void**)&wpl, g_wpl);
    (void)cudaGetSymbolAddress((void**)&yh, g_yh);
    (void)cudaGetSymbolAddress((void**)&yl, g_yl);

    // 0. splits
    splitx_kernel<<<(ROWS * GK / 4) / 256, 256>>>(x);
    wsplit_kernel<<<dim3(QKVW / 32, GK / 32), dim3(32, 8)>>>(w_attn, wah, wal, QKVW);
    wsplit_kernel<<<dim3(Cn / 32, GK / 32), dim3(32, 8)>>>(w_proj, wph, wpl, Cn);
    // 1. qkv = x @ w_attn
    hgemm3_kernel<<<dim3(QKVW / 128, ROWS / 64), 256, GSM>>>(xh, xl, wah, wal, qkvp, QKVW);
    // 2. RoPE + split q,k
    rope_split_kernel<<<(ROWS * 4 * 5 * 64) / 256, 256>>>(cosb, sinb);
    // 3. v split + transpose
    vsplit_kernel<<<dim3(Tn / 32, 4, 8), dim3(32, 8)>>>();
    // 4. attention -> yh/yl
    attn_kernel<<<dim3(Tn / 128, 16, 2), 256, ATT_SMEM>>>();
    // 5. out = y @ w_proj
    hgemm3_kernel<<<dim3(Cn / 128, ROWS / 64), 256, GSM>>>(yh, yl, wph, wpl, out, Cn);
}

// round 8
// speedup vs baseline: 1.1537x; 1.1537x over previous
#include <cuda_runtime.h>
#include <cuda_fp16.h>
#include <cstdint>
#include <cstddef>

// ---------------------------------------------------------------------------
// SelfAttention on sm_103, mma.sync fp16 multi-term.
// R8: sm_103 legacy HMMA measured at its hw peak (512 MAC/cyc/SM) across
// R4-R7 -> only MMA COUNT matters. Attention drops the two weight-side
// correction terms (Qh*Kl in S, Ph*Vl in PV), keeping Ql*Kh and Pl*Vh:
// dropped terms are pure fp16 rounding noise of K/V (~2^-12.6 rel).
// GEMMs stay full x3 (mixed acc, R7-proven). Kl/Vl data paths removed.
// ---------------------------------------------------------------------------

#define Tn     2048
#define Cn     2048
#define QKVW   3072          // (16 + 2*4) * 128
#define ROWS   4096          // B*T
#define GK     2048          // K dim of both big GEMMs

typedef __half f16;

__device__ __align__(16) float g_qkv[(size_t)ROWS * QKVW];
__device__ __align__(16) f16  g_xh[(size_t)ROWS * GK];
__device__ __align__(16) f16  g_xl[(size_t)ROWS * GK];
__device__ __align__(16) f16  g_wah[(size_t)QKVW * GK];
__device__ __align__(16) f16  g_wal[(size_t)QKVW * GK];
__device__ __align__(16) f16  g_wph[(size_t)Cn * GK];
__device__ __align__(16) f16  g_wpl[(size_t)Cn * GK];
__device__ __align__(16) f16  g_qh[(size_t)2 * 16 * Tn * 128];
__device__ __align__(16) f16  g_ql[(size_t)2 * 16 * Tn * 128];
__device__ __align__(16) f16  g_kh[(size_t)2 * 4 * Tn * 128];
__device__ __align__(16) f16  g_vth[(size_t)2 * 4 * 128 * Tn];
__device__ __align__(16) f16  g_yh[(size_t)ROWS * Cn];
__device__ __align__(16) f16  g_yl[(size_t)ROWS * Cn];

// 1/sqrt(128) * log2(e): softmax scale + exp->exp2, folded into q
#define QK_SCALE (0.08838834764831845f * 1.4426950408889634f)

// ============================ helpers =======================================
__device__ __forceinline__ float ex2f(float x) {
    float r;
    asm("ex2.approx.ftz.f32 %0, %1;" : "=f"(r) : "f"(x));
    return r;
}
__device__ __forceinline__ uint32_t pkh2(float lo, float hi) {
    __half2 h = __floats2half2_rn(lo, hi);
    return *reinterpret_cast<uint32_t*>(&h);
}
__device__ __forceinline__ float2 uph2(uint32_t u) {
    __half2 h = *reinterpret_cast<__half2*>(&u);
    return __half22float2(h);
}
__device__ __forceinline__ void mma_f32a(float (&d)[4], const uint32_t (&a)[4],
                                         const uint32_t* b) {
    asm volatile(
        "mma.sync.aligned.m16n8k16.row.col.f32.f16.f16.f32 "
        "{%0,%1,%2,%3}, {%4,%5,%6,%7}, {%8,%9}, {%0,%1,%2,%3};"
        : "+f"(d[0]), "+f"(d[1]), "+f"(d[2]), "+f"(d[3])
        : "r"(a[0]), "r"(a[1]), "r"(a[2]), "r"(a[3]), "r"(b[0]), "r"(b[1]));
}
__device__ __forceinline__ void mma_f16a(uint32_t (&d)[2], const uint32_t (&a)[4],
                                         const uint32_t* b) {
    asm volatile(
        "mma.sync.aligned.m16n8k16.row.col.f16.f16.f16.f16 "
        "{%0,%1}, {%2,%3,%4,%5}, {%6,%7}, {%0,%1};"
        : "+r"(d[0]), "+r"(d[1])
        : "r"(a[0]), "r"(a[1]), "r"(a[2]), "r"(a[3]), "r"(b[0]), "r"(b[1]));
}
__device__ __forceinline__ void ldsm4(uint32_t* r, uint32_t a) {
    asm volatile("ldmatrix.sync.aligned.m8n8.x4.shared.b16 {%0,%1,%2,%3}, [%4];"
                 : "=r"(r[0]), "=r"(r[1]), "=r"(r[2]), "=r"(r[3]) : "r"(a));
}
__device__ __forceinline__ uint32_t smem_u32(const void* p) {
    uint32_t a;
    asm("{ .reg .u64 t; cvta.to.shared.u64 t, %1; cvt.u32.u64 %0, t; }"
        : "=r"(a) : "l"(p));
    return a;
}
#define CP16(dst, src) \
    asm volatile("cp.async.cg.shared.global [%0], [%1], 16;" \
                 :: "r"(dst), "l"(src) : "memory")
#define CPCOMMIT() asm volatile("cp.async.commit_group;" ::: "memory")
#define CPWAIT1()  asm volatile("cp.async.wait_group 1;" ::: "memory")
#define CPWAIT0()  asm volatile("cp.async.wait_group 0;" ::: "memory")

// ---------------------------------------------------------------------------
// split x -> f16 hi/lo
// ---------------------------------------------------------------------------
__global__ __launch_bounds__(256) void splitx_kernel(const float* __restrict__ x) {
    size_t i = ((size_t)blockIdx.x * 256 + threadIdx.x) * 4;
    float4 v = *(const float4*)(x + i);
    f16 h0 = __float2half_rn(v.x), h1 = __float2half_rn(v.y);
    f16 h2 = __float2half_rn(v.z), h3 = __float2half_rn(v.w);
    f16 l0 = __float2half_rn(v.x - __half2float(h0));
    f16 l1 = __float2half_rn(v.y - __half2float(h1));
    f16 l2 = __float2half_rn(v.z - __half2float(h2));
    f16 l3 = __float2half_rn(v.w - __half2float(h3));
    g_xh[i] = h0; g_xh[i + 1] = h1; g_xh[i + 2] = h2; g_xh[i + 3] = h3;
    g_xl[i] = l0; g_xl[i + 1] = l1; g_xl[i + 2] = l2; g_xl[i + 3] = l3;
}

// ---------------------------------------------------------------------------
// transpose + split weights: in [2048][Ccols] fp32 -> hi/lo [Ccols][2048] f16
// ---------------------------------------------------------------------------
__global__ __launch_bounds__(256) void wsplit_kernel(
    const float* __restrict__ in, f16* __restrict__ hi, f16* __restrict__ lo,
    int Ccols)
{
    __shared__ float tb[32][33];
    const int bx = blockIdx.x * 32, by = blockIdx.y * 32;
    const int tx = threadIdx.x, ty = threadIdx.y;
#pragma unroll
    for (int j = 0; j < 32; j += 8)
        tb[ty + j][tx] = in[(size_t)(by + ty + j) * Ccols + bx + tx];
    __syncthreads();
#pragma unroll
    for (int j = 0; j < 32; j += 8) {
        float v = tb[tx][ty + j];
        size_t o = (size_t)(bx + ty + j) * GK + by + tx;
        f16 h = __float2half_rn(v);
        hi[o] = h;
        lo[o] = __float2half_rn(v - __half2float(h));
    }
}

// ---------------------------------------------------------------------------
// fp16x3 mixed-acc GEMM (R7-proven): C[M,N] = A[M,2048] @ BT[N,2048]^T.
// CTA tile 64x128, kchunk 32, cp.async double buffer, 8 warps (2m x 4n).
// ---------------------------------------------------------------------------
#define GS_STAGE 30720
#define GSM (2 * GS_STAGE)

__global__ __launch_bounds__(256, 2) void hgemm3_kernel(
    const f16* __restrict__ Ah, const f16* __restrict__ Al,
    const f16* __restrict__ Bh, const f16* __restrict__ Bl,
    float* __restrict__ C, int N)
{
    extern __shared__ char sm[];
    const uint32_t sb = smem_u32(sm);
    const int tid = threadIdx.x;
    const int lane = tid & 31, wid = tid >> 5;
    const int lg = lane >> 2, tq = lane & 3;
    const int mi = wid & 1, ni = wid >> 1;
    const size_t m0 = (size_t)blockIdx.y * 64, n0 = (size_t)blockIdx.x * 128;

    const uint32_t abase =
        (uint32_t)((mi * 32 + (lane & 15)) * 80 + (lane >> 4) * 16);
    const uint32_t bbase =
        (uint32_t)(10240 + (ni * 32 + (lane & 7) + ((lane >> 4) * 8)) * 80 +
                   ((lane >> 3) & 1) * 16);

    const int ar = tid >> 2;
    const int ac = tid & 3;
    const f16* pAh = Ah + (m0 + ar) * GK + ac * 8;
    const f16* pAl = Al + (m0 + ar) * GK + ac * 8;
    const f16* pBh = Bh + (n0 + ar) * GK + ac * 8;
    const f16* pBl = Bl + (n0 + ar) * GK + ac * 8;
    const uint32_t sdA = sb + ar * 80 + ac * 16;
    const uint32_t sdB = sb + 10240 + ar * 80 + ac * 16;

    float c[2][4][4];
    uint32_t cc[2][4][2];
#pragma unroll
    for (int a = 0; a < 2; a++)
#pragma unroll
        for (int b = 0; b < 4; b++) {
#pragma unroll
            for (int d = 0; d < 4; d++) c[a][b][d] = 0.f;
            cc[a][b][0] = 0u; cc[a][b][1] = 0u;
        }

    {
        CP16(sdA,         pAh);
        CP16(sdA + 5120,  pAl);
        CP16(sdB,              pBh);
        CP16(sdB + 64 * 80,    pBh + (size_t)64 * GK);
        CP16(sdB + 10240,           pBl);
        CP16(sdB + 10240 + 64 * 80, pBl + (size_t)64 * GK);
        CPCOMMIT();
    }

#pragma unroll 1
    for (int kt = 0; kt < GK / 32; kt++) {
        const int s = kt & 1;
        if (kt + 1 < GK / 32) {
            uint32_t dA = sdA + (s ^ 1) * GS_STAGE;
            uint32_t dB = sdB + (s ^ 1) * GS_STAGE;
            size_t off = (size_t)(kt + 1) * 32;
            CP16(dA,         pAh + off);
            CP16(dA + 5120,  pAl + off);
            CP16(dB,              pBh + off);
            CP16(dB + 64 * 80,    pBh + off + (size_t)64 * GK);
            CP16(dB + 10240,           pBl + off);
            CP16(dB + 10240 + 64 * 80, pBl + off + (size_t)64 * GK);
            CPCOMMIT();
            CPWAIT1();
        } else {
            CPWAIT0();
        }
        __syncthreads();

        const uint32_t stg = sb + s * GS_STAGE;
#pragma unroll
        for (int kk = 0; kk < 2; kk++) {
            uint32_t ah[2][4], al[2][4];
#pragma unroll
            for (int mt = 0; mt < 2; mt++) {
                uint32_t aa = stg + abase + mt * (16 * 80) + kk * 32;
                ldsm4(ah[mt], aa);
                ldsm4(al[mt], aa + 5120);
            }
            uint32_t bb[4][2];
#pragma unroll
            for (int p = 0; p < 2; p++)
                ldsm4(&bb[2 * p][0], stg + bbase + p * (16 * 80) + kk * 32);
#pragma unroll
            for (int mt = 0; mt < 2; mt++)
#pragma unroll
                for (int nt = 0; nt < 4; nt++) mma_f32a(c[mt][nt], ah[mt], bb[nt]);
#pragma unroll
            for (int mt = 0; mt < 2; mt++)
#pragma unroll
                for (int nt = 0; nt < 4; nt++) mma_f16a(cc[mt][nt], al[mt], bb[nt]);
#pragma unroll
            for (int p = 0; p < 2; p++)
                ldsm4(&bb[2 * p][0], stg + bbase + 10240 + p * (16 * 80) + kk * 32);
#pragma unroll
            for (int mt = 0; mt < 2; mt++)
#pragma unroll
                for (int nt = 0; nt < 4; nt++) mma_f16a(cc[mt][nt], ah[mt], bb[nt]);
        }
        __syncthreads();
    }

#pragma unroll
    for (int mt = 0; mt < 2; mt++) {
        size_t r0 = m0 + mi * 32 + mt * 16 + lg;
#pragma unroll
        for (int nt = 0; nt < 4; nt++) {
            float2 f0 = uph2(cc[mt][nt][0]);
            float2 f1 = uph2(cc[mt][nt][1]);
            size_t col = n0 + ni * 32 + nt * 8 + tq * 2;
            *(float2*)(C + r0 * N + col) =
                make_float2(c[mt][nt][0] + f0.x, c[mt][nt][1] + f0.y);
            *(float2*)(C + (r0 + 8) * N + col) =
                make_float2(c[mt][nt][2] + f1.x, c[mt][nt][3] + f1.y);
        }
    }
}

// ---------------------------------------------------------------------------
// RoPE + f16 split: q (slots 0-3, scaled) -> g_qh/ql; k (slot 4) -> g_kh (hi only)
// ---------------------------------------------------------------------------
__global__ __launch_bounds__(256) void rope_split_kernel(
    const float* __restrict__ cosb, const float* __restrict__ sinb)
{
    int idx = blockIdx.x * 256 + threadIdx.x;     // ROWS*4*5*64
    int d = idx & 63;
    int rg = idx >> 6;
    int slot = rg % 5;
    int q5 = rg / 5;
    int grp = q5 & 3;
    int row = q5 >> 2;
    int b = row >> 11, t = row & (Tn - 1);

    const float* p = g_qkv + (size_t)row * QKVW + grp * 768 + slot * 128 + d;
    float x1 = p[0], x2 = p[64];
    float cc = cosb[t * 64 + d], ss = sinb[t * 64 + d];
    float o1 = x1 * cc - x2 * ss;
    float o2 = x1 * ss + x2 * cc;

    if (slot < 4) {
        o1 *= QK_SCALE; o2 *= QK_SCALE;
        int head = grp * 4 + slot;
        size_t base = ((size_t)(b * 16 + head) * Tn + t) * 128 + d;
        f16 h1 = __float2half_rn(o1), h2 = __float2half_rn(o2);
        g_qh[base]      = h1;
        g_qh[base + 64] = h2;
        g_ql[base]      = __float2half_rn(o1 - __half2float(h1));
        g_ql[base + 64] = __float2half_rn(o2 - __half2float(h2));
    } else {
        size_t base = ((size_t)(b * 4 + grp) * Tn + t) * 128 + d;
        g_kh[base]      = __float2half_rn(o1);
        g_kh[base + 64] = __float2half_rn(o2);
    }
}

// ---------------------------------------------------------------------------
// v: transpose -> g_vth [b][g][d][t] (hi only)
// ---------------------------------------------------------------------------
__global__ __launch_bounds__(256) void vsplit_kernel() {
    __shared__ float tb[32][33];
    const int bg = blockIdx.z;
    const int t0 = blockIdx.x * 32, d0 = blockIdx.y * 32;
    const int tx = threadIdx.x, ty = threadIdx.y;
    const int b = bg >> 2, grp = bg & 3;
#pragma unroll
    for (int j = 0; j < 32; j += 8)
        tb[ty + j][tx] = g_qkv[((size_t)b * Tn + t0 + ty + j) * QKVW +
                               grp * 768 + 640 + d0 + tx];
    __syncthreads();
#pragma unroll
    for (int j = 0; j < 32; j += 8) {
        float v = tb[tx][ty + j];
        size_t o = ((size_t)bg * 128 + d0 + ty + j) * Tn + t0 + tx;
        g_vth[o] = __float2half_rn(v);
    }
}

// ---------------------------------------------------------------------------
// Flash attention, fp16 2-term (S: Qh*Kh + Ql*Kh; PV: Ph*Vh + Pl*Vh).
// CTA = (qb, h, b): 128 q rows, 8 warps x m16. Key tiles of 64.
// smem: Qh/Ql [128 x 272B], Kh [64 x 272B], Vth [128 d x 144B].
// ---------------------------------------------------------------------------
#define AQ_H 0
#define AQ_L 34816
#define AK_H 69632
#define AV_H 87040
#define ATT_SMEM 105472

__global__ __launch_bounds__(256, 1) void attn_kernel() {
    extern __shared__ char sm[];
    const uint32_t sb = smem_u32(sm);
    const int tid = threadIdx.x;
    const int lane = tid & 31, wid = tid >> 5;
    const int lg = lane >> 2, tq = lane & 3;
    const int qb = blockIdx.x, h = blockIdx.y, b = blockIdx.z;
    const int grp = h >> 2;

    const uint32_t qbase = sb + AQ_H + (wid * 16 + (lane & 15)) * 272 +
                           (lane >> 4) * 16;
    const uint32_t kbase = sb + AK_H + ((lane & 7) + ((lane >> 4) * 8)) * 272 +
                           ((lane >> 3) & 1) * 16;
    const uint32_t vbase = sb + AV_H + ((lane & 7) + ((lane >> 4) * 8)) * 144 +
                           ((lane >> 3) & 1) * 16;

    // load Q (hi/lo), 128 x 128 f16 each
    {
        const f16* qhp = g_qh + ((size_t)(b * 16 + h) * Tn + qb * 128) * 128;
        const f16* qlp = g_ql + ((size_t)(b * 16 + h) * Tn + qb * 128) * 128;
#pragma unroll
        for (int it = 0; it < 8; it++) {
            int idx = it * 256 + tid;
            int r = idx >> 4, hx = idx & 15;
            *(uint4*)(sm + AQ_H + r * 272 + hx * 16) = *(const uint4*)(qhp + (size_t)r * 128 + hx * 8);
            *(uint4*)(sm + AQ_L + r * 272 + hx * 16) = *(const uint4*)(qlp + (size_t)r * 128 + hx * 8);
        }
    }

    float o[16][4];
#pragma unroll
    for (int i = 0; i < 16; i++)
#pragma unroll
        for (int j = 0; j < 4; j++) o[i][j] = 0.f;
    float m0 = __int_as_float(0xff800000), m1 = m0;
    float l0 = 0.f, l1 = 0.f;

    const f16* khp = g_kh + (size_t)(b * 4 + grp) * Tn * 128;
    const f16* vhp = g_vth + (size_t)(b * 4 + grp) * 128 * Tn;

#pragma unroll 1
    for (int kt = 0; kt < Tn / 64; kt++) {
        __syncthreads();
#pragma unroll
        for (int it = 0; it < 4; it++) {
            int idx = it * 256 + tid;
            int r = idx >> 4, hx = idx & 15;
            size_t go = ((size_t)kt * 64 + r) * 128 + hx * 8;
            *(uint4*)(sm + AK_H + r * 272 + hx * 16) = *(const uint4*)(khp + go);
        }
#pragma unroll
        for (int it = 0; it < 4; it++) {
            int idx = it * 256 + tid;
            int r = idx >> 3, hx = idx & 7;
            size_t go = (size_t)r * Tn + kt * 64 + hx * 8;
            *(uint4*)(sm + AV_H + r * 144 + hx * 16) = *(const uint4*)(vhp + go);
        }
        __syncthreads();

        // ---- S = (Qh + Ql) Kh^T, f32 acc ----
        float s[8][4];
#pragma unroll
        for (int i = 0; i < 8; i++)
#pragma unroll
            for (int j = 0; j < 4; j++) s[i][j] = 0.f;

#pragma unroll
        for (int kk = 0; kk < 8; kk++) {
            uint32_t qah[4], qal[4];
            ldsm4(qah, qbase + kk * 32);
            ldsm4(qal, qbase + (AQ_L - AQ_H) + kk * 32);
            uint32_t kb[8][2];
#pragma unroll
            for (int p = 0; p < 4; p++)
                ldsm4(&kb[2 * p][0], kbase + p * (16 * 272) + kk * 32);
#pragma unroll
            for (int nt = 0; nt < 8; nt++) mma_f32a(s[nt], qah, kb[nt]);
#pragma unroll
            for (int nt = 0; nt < 8; nt++) mma_f32a(s[nt], qal, kb[nt]);
        }

        // ---- online softmax (2 rows per lane: lg, lg+8) ----
        float mx0 = s[0][0], mx1 = s[0][2];
#pragma unroll
        for (int nt = 0; nt < 8; nt++) {
            mx0 = fmaxf(mx0, fmaxf(s[nt][0], s[nt][1]));
            mx1 = fmaxf(mx1, fmaxf(s[nt][2], s[nt][3]));
        }
        mx0 = fmaxf(mx0, __shfl_xor_sync(0xffffffffu, mx0, 1));
        mx0 = fmaxf(mx0, __shfl_xor_sync(0xffffffffu, mx0, 2));
        mx1 = fmaxf(mx1, __shfl_xor_sync(0xffffffffu, mx1, 1));
        mx1 = fmaxf(mx1, __shfl_xor_sync(0xffffffffu, mx1, 2));
        float mn0 = fmaxf(m0, mx0), mn1 = fmaxf(m1, mx1);
        float cr0 = ex2f(m0 - mn0), cr1 = ex2f(m1 - mn1);
        m0 = mn0; m1 = mn1;
        float sum0 = 0.f, sum1 = 0.f;
#pragma unroll
        for (int nt = 0; nt < 8; nt++) {
            s[nt][0] = ex2f(s[nt][0] - mn0);
            s[nt][1] = ex2f(s[nt][1] - mn0);
            s[nt][2] = ex2f(s[nt][2] - mn1);
            s[nt][3] = ex2f(s[nt][3] - mn1);
            sum0 += s[nt][0] + s[nt][1];
            sum1 += s[nt][2] + s[nt][3];
        }
        sum0 += __shfl_xor_sync(0xffffffffu, sum0, 1);
        sum0 += __shfl_xor_sync(0xffffffffu, sum0, 2);
        sum1 += __shfl_xor_sync(0xffffffffu, sum1, 1);
        sum1 += __shfl_xor_sync(0xffffffffu, sum1, 2);
        l0 = l0 * cr0 + sum0;
        l1 = l1 * cr1 + sum1;
#pragma unroll
        for (int nt = 0; nt < 16; nt++) {
            o[nt][0] *= cr0; o[nt][1] *= cr0;
            o[nt][2] *= cr1; o[nt][3] *= cr1;
        }

        // ---- O += (Ph + Pl) Vh, f32 acc ----
#pragma unroll
        for (int kk = 0; kk < 4; kk++) {
            uint32_t ph[4], pl[4];
#pragma unroll
            for (int q2 = 0; q2 < 2; q2++) {
                float e0 = s[2 * kk + q2][0], e1 = s[2 * kk + q2][1];
                ph[2 * q2] = pkh2(e0, e1);
                float2 hp = uph2(ph[2 * q2]);
                pl[2 * q2] = pkh2(e0 - hp.x, e1 - hp.y);
                e0 = s[2 * kk + q2][2]; e1 = s[2 * kk + q2][3];
                ph[2 * q2 + 1] = pkh2(e0, e1);
                hp = uph2(ph[2 * q2 + 1]);
                pl[2 * q2 + 1] = pkh2(e0 - hp.x, e1 - hp.y);
            }
#pragma unroll
            for (int blk = 0; blk < 2; blk++) {
                uint32_t vb[8][2];
#pragma unroll
                for (int p = 0; p < 4; p++)
                    ldsm4(&vb[2 * p][0], vbase + (blk * 64 + p * 16) * 144 + kk * 32);
#pragma unroll
                for (int j = 0; j < 8; j++) mma_f32a(o[blk * 8 + j], ph, vb[j]);
#pragma unroll
                for (int j = 0; j < 8; j++) mma_f32a(o[blk * 8 + j], pl, vb[j]);
            }
        }
    }

    // ---- epilogue: y = O / l, split to f16 hi/lo ----
    float i0 = 1.f / l0, i1 = 1.f / l1;
    size_t row0 = (size_t)b * Tn + qb * 128 + wid * 16 + lg;
#pragma unroll
    for (int nt = 0; nt < 16; nt++) {
        int col = h * 128 + nt * 8 + tq * 2;
        float v0 = o[nt][0] * i0, v1 = o[nt][1] * i0;
        uint32_t hh = pkh2(v0, v1);
        float2 hp = uph2(hh);
        *(uint32_t*)(g_yh + row0 * Cn + col) = hh;
        *(uint32_t*)(g_yl + row0 * Cn + col) = pkh2(v0 - hp.x, v1 - hp.y);
        v0 = o[nt][2] * i1; v1 = o[nt][3] * i1;
        hh = pkh2(v0, v1);
        hp = uph2(hh);
        *(uint32_t*)(g_yh + (row0 + 8) * Cn + col) = hh;
        *(uint32_t*)(g_yl + (row0 + 8) * Cn + col) = pkh2(v0 - hp.x, v1 - hp.y);
    }
}

// ---------------------------------------------------------------------------
extern "C" void kernel_launch(void* const* d_in, const int* in_sizes, int n_in,
                              void* d_out, int out_size) {
    const float* x      = (const float*)d_in[0];
    const float* cosb   = (const float*)d_in[1];
    const float* sinb   = (const float*)d_in[2];
    const float* w_attn = (const float*)d_in[3];
    const float* w_proj = (const float*)d_in[4];
    float* out = (float*)d_out;
    (void)in_sizes; (void)n_in; (void)out_size;

    (void)cudaFuncSetAttribute(hgemm3_kernel,
                               cudaFuncAttributeMaxDynamicSharedMemorySize, GSM);
    (void)cudaFuncSetAttribute(attn_kernel,
                               cudaFuncAttributeMaxDynamicSharedMemorySize, ATT_SMEM);

    float* qkvp = nullptr;
    f16 *xh, *xl, *wah, *wal, *wph, *wpl, *yh, *yl;
    (void)cudaGetSymbolAddress((void**)&qkvp, g_qkv);
    (void)cudaGetSymbolAddress((void**)&xh, g_xh);
    (void)cudaGetSymbolAddress((void**)&xl, g_xl);
    (void)cudaGetSymbolAddress((void**)&wah, g_wah);
    (void)cudaGetSymbolAddress((void**)&wal, g_wal);
    (void)cudaGetSymbolAddress((void**)&wph, g_wph);
    (void)cudaGetSymbolAddress((void**)&wpl, g_wpl);
    (void)cudaGetSymbolAddress((void**)&yh, g_yh);
    (void)cudaGetSymbolAddress((void**)&yl, g_yl);

    // 0. splits
    splitx_kernel<<<(ROWS * GK / 4) / 256, 256>>>(x);
    wsplit_kernel<<<dim3(QKVW / 32, GK / 32), dim3(32, 8)>>>(w_attn, wah, wal, QKVW);
    wsplit_kernel<<<dim3(Cn / 32, GK / 32), dim3(32, 8)>>>(w_proj, wph, wpl, Cn);
    // 1. qkv = x @ w_attn
    hgemm3_kernel<<<dim3(QKVW / 128, ROWS / 64), 256, GSM>>>(xh, xl, wah, wal, qkvp, QKVW);
    // 2. RoPE + split q (hi/lo), k (hi)
    rope_split_kernel<<<(ROWS * 4 * 5 * 64) / 256, 256>>>(cosb, sinb);
    // 3. v transpose (hi)
    vsplit_kernel<<<dim3(Tn / 32, 4, 8), dim3(32, 8)>>>();
    // 4. attention -> yh/yl
    attn_kernel<<<dim3(Tn / 128, 16, 2), 256, ATT_SMEM>>>();
    // 5. out = y @ w_proj
    hgemm3_kernel<<<dim3(Cn / 128, ROWS / 64), 256, GSM>>>(yh, yl, wph, wpl, out, Cn);
}

// round 9
// speedup vs baseline: 1.5116x; 1.3101x over previous
#include <cuda_runtime.h>
#include <cuda_fp16.h>
#include <cstdint>
#include <cstddef>

// ---------------------------------------------------------------------------
// SelfAttention on sm_103, mma.sync fp16 multi-term.
// R9: GEMMs drop the x*w_lo term (weights effectively fp16-rounded, adds
// ~2.8e-4 RMS each, budget-checked vs 1e-3 gate). Both remaining terms
// (xh*wh, xl*wh) use f32 accumulate (acc type is rate-neutral, R7).
// Attention keeps its 2-term scheme from R8 (error floor protection).
// Legacy HMMA is at its hw peak -> time scales with MMA count: GEMMs at 2/3.
// ---------------------------------------------------------------------------

#define Tn     2048
#define Cn     2048
#define QKVW   3072          // (16 + 2*4) * 128
#define ROWS   4096          // B*T
#define GK     2048          // K dim of both big GEMMs

typedef __half f16;

__device__ __align__(16) float g_qkv[(size_t)ROWS * QKVW];
__device__ __align__(16) f16  g_xh[(size_t)ROWS * GK];
__device__ __align__(16) f16  g_xl[(size_t)ROWS * GK];
__device__ __align__(16) f16  g_wah[(size_t)QKVW * GK];
__device__ __align__(16) f16  g_wph[(size_t)Cn * GK];
__device__ __align__(16) f16  g_qh[(size_t)2 * 16 * Tn * 128];
__device__ __align__(16) f16  g_ql[(size_t)2 * 16 * Tn * 128];
__device__ __align__(16) f16  g_kh[(size_t)2 * 4 * Tn * 128];
__device__ __align__(16) f16  g_vth[(size_t)2 * 4 * 128 * Tn];
__device__ __align__(16) f16  g_yh[(size_t)ROWS * Cn];
__device__ __align__(16) f16  g_yl[(size_t)ROWS * Cn];

// 1/sqrt(128) * log2(e): softmax scale + exp->exp2, folded into q
#define QK_SCALE (0.08838834764831845f * 1.4426950408889634f)

// ============================ helpers =======================================
__device__ __forceinline__ float ex2f(float x) {
    float r;
    asm("ex2.approx.ftz.f32 %0, %1;" : "=f"(r) : "f"(x));
    return r;
}
__device__ __forceinline__ uint32_t pkh2(float lo, float hi) {
    __half2 h = __floats2half2_rn(lo, hi);
    return *reinterpret_cast<uint32_t*>(&h);
}
__device__ __forceinline__ float2 uph2(uint32_t u) {
    __half2 h = *reinterpret_cast<__half2*>(&u);
    return __half22float2(h);
}
__device__ __forceinline__ void mma_f32a(float (&d)[4], const uint32_t (&a)[4],
                                         const uint32_t* b) {
    asm volatile(
        "mma.sync.aligned.m16n8k16.row.col.f32.f16.f16.f32 "
        "{%0,%1,%2,%3}, {%4,%5,%6,%7}, {%8,%9}, {%0,%1,%2,%3};"
        : "+f"(d[0]), "+f"(d[1]), "+f"(d[2]), "+f"(d[3])
        : "r"(a[0]), "r"(a[1]), "r"(a[2]), "r"(a[3]), "r"(b[0]), "r"(b[1]));
}
__device__ __forceinline__ void ldsm4(uint32_t* r, uint32_t a) {
    asm volatile("ldmatrix.sync.aligned.m8n8.x4.shared.b16 {%0,%1,%2,%3}, [%4];"
                 : "=r"(r[0]), "=r"(r[1]), "=r"(r[2]), "=r"(r[3]) : "r"(a));
}
__device__ __forceinline__ uint32_t smem_u32(const void* p) {
    uint32_t a;
    asm("{ .reg .u64 t; cvta.to.shared.u64 t, %1; cvt.u32.u64 %0, t; }"
        : "=r"(a) : "l"(p));
    return a;
}
#define CP16(dst, src) \
    asm volatile("cp.async.cg.shared.global [%0], [%1], 16;" \
                 :: "r"(dst), "l"(src) : "memory")
#define CPCOMMIT() asm volatile("cp.async.commit_group;" ::: "memory")
#define CPWAIT1()  asm volatile("cp.async.wait_group 1;" ::: "memory")
#define CPWAIT0()  asm volatile("cp.async.wait_group 0;" ::: "memory")

// ---------------------------------------------------------------------------
// split x -> f16 hi/lo
// ---------------------------------------------------------------------------
__global__ __launch_bounds__(256) void splitx_kernel(const float* __restrict__ x) {
    size_t i = ((size_t)blockIdx.x * 256 + threadIdx.x) * 4;
    float4 v = *(const float4*)(x + i);
    f16 h0 = __float2half_rn(v.x), h1 = __float2half_rn(v.y);
    f16 h2 = __float2half_rn(v.z), h3 = __float2half_rn(v.w);
    f16 l0 = __float2half_rn(v.x - __half2float(h0));
    f16 l1 = __float2half_rn(v.y - __half2float(h1));
    f16 l2 = __float2half_rn(v.z - __half2float(h2));
    f16 l3 = __float2half_rn(v.w - __half2float(h3));
    g_xh[i] = h0; g_xh[i + 1] = h1; g_xh[i + 2] = h2; g_xh[i + 3] = h3;
    g_xl[i] = l0; g_xl[i + 1] = l1; g_xl[i + 2] = l2; g_xl[i + 3] = l3;
}

// ---------------------------------------------------------------------------
// transpose weights to fp16 (hi only): in [2048][Ccols] fp32 -> [Ccols][2048]
// ---------------------------------------------------------------------------
__global__ __launch_bounds__(256) void wsplit_kernel(
    const float* __restrict__ in, f16* __restrict__ hi, int Ccols)
{
    __shared__ float tb[32][33];
    const int bx = blockIdx.x * 32, by = blockIdx.y * 32;
    const int tx = threadIdx.x, ty = threadIdx.y;
#pragma unroll
    for (int j = 0; j < 32; j += 8)
        tb[ty + j][tx] = in[(size_t)(by + ty + j) * Ccols + bx + tx];
    __syncthreads();
#pragma unroll
    for (int j = 0; j < 32; j += 8) {
        float v = tb[tx][ty + j];
        hi[(size_t)(bx + ty + j) * GK + by + tx] = __float2half_rn(v);
    }
}

// ---------------------------------------------------------------------------
// fp16 2-term GEMM: C[M,N] = (Ah + Al) @ Bh^T, f32 accumulate.
// CTA tile 64x128, kchunk 32, cp.async double buffer, 8 warps (2m x 4n).
// smem stage: Ah@0(5120) Al@5120 Bh@10240(10240) = 20480 B.
// ---------------------------------------------------------------------------
#define GS_STAGE 20480
#define GSM (2 * GS_STAGE)

__global__ __launch_bounds__(256, 2) void hgemm2_kernel(
    const f16* __restrict__ Ah, const f16* __restrict__ Al,
    const f16* __restrict__ Bh,
    float* __restrict__ C, int N)
{
    extern __shared__ char sm[];
    const uint32_t sb = smem_u32(sm);
    const int tid = threadIdx.x;
    const int lane = tid & 31, wid = tid >> 5;
    const int lg = lane >> 2, tq = lane & 3;
    const int mi = wid & 1, ni = wid >> 1;
    const size_t m0 = (size_t)blockIdx.y * 64, n0 = (size_t)blockIdx.x * 128;

    const uint32_t abase =
        (uint32_t)((mi * 32 + (lane & 15)) * 80 + (lane >> 4) * 16);
    const uint32_t bbase =
        (uint32_t)(10240 + (ni * 32 + (lane & 7) + ((lane >> 4) * 8)) * 80 +
                   ((lane >> 3) & 1) * 16);

    const int ar = tid >> 2;
    const int ac = tid & 3;
    const f16* pAh = Ah + (m0 + ar) * GK + ac * 8;
    const f16* pAl = Al + (m0 + ar) * GK + ac * 8;
    const f16* pBh = Bh + (n0 + ar) * GK + ac * 8;
    const uint32_t sdA = sb + ar * 80 + ac * 16;
    const uint32_t sdB = sb + 10240 + ar * 80 + ac * 16;

    float c[2][4][4];
#pragma unroll
    for (int a = 0; a < 2; a++)
#pragma unroll
        for (int b = 0; b < 4; b++)
#pragma unroll
            for (int d = 0; d < 4; d++) c[a][b][d] = 0.f;

    {
        CP16(sdA,         pAh);
        CP16(sdA + 5120,  pAl);
        CP16(sdB,           pBh);
        CP16(sdB + 64 * 80, pBh + (size_t)64 * GK);
        CPCOMMIT();
    }

#pragma unroll 1
    for (int kt = 0; kt < GK / 32; kt++) {
        const int s = kt & 1;
        if (kt + 1 < GK / 32) {
            uint32_t dA = sdA + (s ^ 1) * GS_STAGE;
            uint32_t dB = sdB + (s ^ 1) * GS_STAGE;
            size_t off = (size_t)(kt + 1) * 32;
            CP16(dA,         pAh + off);
            CP16(dA + 5120,  pAl + off);
            CP16(dB,           pBh + off);
            CP16(dB + 64 * 80, pBh + off + (size_t)64 * GK);
            CPCOMMIT();
            CPWAIT1();
        } else {
            CPWAIT0();
        }
        __syncthreads();

        const uint32_t stg = sb + s * GS_STAGE;
#pragma unroll
        for (int kk = 0; kk < 2; kk++) {
            uint32_t ah[2][4], al[2][4];
#pragma unroll
            for (int mt = 0; mt < 2; mt++) {
                uint32_t aa = stg + abase + mt * (16 * 80) + kk * 32;
                ldsm4(ah[mt], aa);
                ldsm4(al[mt], aa + 5120);
            }
            uint32_t bb[4][2];
#pragma unroll
            for (int p = 0; p < 2; p++)
                ldsm4(&bb[2 * p][0], stg + bbase + p * (16 * 80) + kk * 32);
            // term 1: ah * bh
#pragma unroll
            for (int mt = 0; mt < 2; mt++)
#pragma unroll
                for (int nt = 0; nt < 4; nt++) mma_f32a(c[mt][nt], ah[mt], bb[nt]);
            // term 2: al * bh
#pragma unroll
            for (int mt = 0; mt < 2; mt++)
#pragma unroll
                for (int nt = 0; nt < 4; nt++) mma_f32a(c[mt][nt], al[mt], bb[nt]);
        }
        __syncthreads();
    }

#pragma unroll
    for (int mt = 0; mt < 2; mt++) {
        size_t r0 = m0 + mi * 32 + mt * 16 + lg;
#pragma unroll
        for (int nt = 0; nt < 4; nt++) {
            size_t col = n0 + ni * 32 + nt * 8 + tq * 2;
            *(float2*)(C + r0 * N + col) = make_float2(c[mt][nt][0], c[mt][nt][1]);
            *(float2*)(C + (r0 + 8) * N + col) = make_float2(c[mt][nt][2], c[mt][nt][3]);
        }
    }
}

// ---------------------------------------------------------------------------
// RoPE + f16 split: q (slots 0-3, scaled) -> g_qh/ql; k (slot 4) -> g_kh (hi)
// ---------------------------------------------------------------------------
__global__ __launch_bounds__(256) void rope_split_kernel(
    const float* __restrict__ cosb, const float* __restrict__ sinb)
{
    int idx = blockIdx.x * 256 + threadIdx.x;     // ROWS*4*5*64
    int d = idx & 63;
    int rg = idx >> 6;
    int slot = rg % 5;
    int q5 = rg / 5;
    int grp = q5 & 3;
    int row = q5 >> 2;
    int b = row >> 11, t = row & (Tn - 1);

    const float* p = g_qkv + (size_t)row * QKVW + grp * 768 + slot * 128 + d;
    float x1 = p[0], x2 = p[64];
    float cc = cosb[t * 64 + d], ss = sinb[t * 64 + d];
    float o1 = x1 * cc - x2 * ss;
    float o2 = x1 * ss + x2 * cc;

    if (slot < 4) {
        o1 *= QK_SCALE; o2 *= QK_SCALE;
        int head = grp * 4 + slot;
        size_t base = ((size_t)(b * 16 + head) * Tn + t) * 128 + d;
        f16 h1 = __float2half_rn(o1), h2 = __float2half_rn(o2);
        g_qh[base]      = h1;
        g_qh[base + 64] = h2;
        g_ql[base]      = __float2half_rn(o1 - __half2float(h1));
        g_ql[base + 64] = __float2half_rn(o2 - __half2float(h2));
    } else {
        size_t base = ((size_t)(b * 4 + grp) * Tn + t) * 128 + d;
        g_kh[base]      = __float2half_rn(o1);
        g_kh[base + 64] = __float2half_rn(o2);
    }
}

// ---------------------------------------------------------------------------
// v: transpose -> g_vth [b][g][d][t] (hi only)
// ---------------------------------------------------------------------------
__global__ __launch_bounds__(256) void vsplit_kernel() {
    __shared__ float tb[32][33];
    const int bg = blockIdx.z;
    const int t0 = blockIdx.x * 32, d0 = blockIdx.y * 32;
    const int tx = threadIdx.x, ty = threadIdx.y;
    const int b = bg >> 2, grp = bg & 3;
#pragma unroll
    for (int j = 0; j < 32; j += 8)
        tb[ty + j][tx] = g_qkv[((size_t)b * Tn + t0 + ty + j) * QKVW +
                               grp * 768 + 640 + d0 + tx];
    __syncthreads();
#pragma unroll
    for (int j = 0; j < 32; j += 8) {
        float v = tb[tx][ty + j];
        size_t o = ((size_t)bg * 128 + d0 + ty + j) * Tn + t0 + tx;
        g_vth[o] = __float2half_rn(v);
    }
}

// ---------------------------------------------------------------------------
// Flash attention, fp16 2-term (S: (Qh+Ql)*Kh; PV: (Ph+Pl)*Vh), f32 acc.
// CTA = (qb, h, b): 128 q rows, 8 warps x m16. Key tiles of 64.
// smem: Qh/Ql [128 x 272B], Kh [64 x 272B], Vth [128 d x 144B].
// ---------------------------------------------------------------------------
#define AQ_H 0
#define AQ_L 34816
#define AK_H 69632
#define AV_H 87040
#define ATT_SMEM 105472

__global__ __launch_bounds__(256, 1) void attn_kernel() {
    extern __shared__ char sm[];
    const uint32_t sb = smem_u32(sm);
    const int tid = threadIdx.x;
    const int lane = tid & 31, wid = tid >> 5;
    const int lg = lane >> 2, tq = lane & 3;
    const int qb = blockIdx.x, h = blockIdx.y, b = blockIdx.z;
    const int grp = h >> 2;

    const uint32_t qbase = sb + AQ_H + (wid * 16 + (lane & 15)) * 272 +
                           (lane >> 4) * 16;
    const uint32_t kbase = sb + AK_H + ((lane & 7) + ((lane >> 4) * 8)) * 272 +
                           ((lane >> 3) & 1) * 16;
    const uint32_t vbase = sb + AV_H + ((lane & 7) + ((lane >> 4) * 8)) * 144 +
                           ((lane >> 3) & 1) * 16;

    // load Q (hi/lo), 128 x 128 f16 each
    {
        const f16* qhp = g_qh + ((size_t)(b * 16 + h) * Tn + qb * 128) * 128;
        const f16* qlp = g_ql + ((size_t)(b * 16 + h) * Tn + qb * 128) * 128;
#pragma unroll
        for (int it = 0; it < 8; it++) {
            int idx = it * 256 + tid;
            int r = idx >> 4, hx = idx & 15;
            *(uint4*)(sm + AQ_H + r * 272 + hx * 16) = *(const uint4*)(qhp + (size_t)r * 128 + hx * 8);
            *(uint4*)(sm + AQ_L + r * 272 + hx * 16) = *(const uint4*)(qlp + (size_t)r * 128 + hx * 8);
        }
    }

    float o[16][4];
#pragma unroll
    for (int i = 0; i < 16; i++)
#pragma unroll
        for (int j = 0; j < 4; j++) o[i][j] = 0.f;
    float m0 = __int_as_float(0xff800000), m1 = m0;
    float l0 = 0.f, l1 = 0.f;

    const f16* khp = g_kh + (size_t)(b * 4 + grp) * Tn * 128;
    const f16* vhp = g_vth + (size_t)(b * 4 + grp) * 128 * Tn;

#pragma unroll 1
    for (int kt = 0; kt < Tn / 64; kt++) {
        __syncthreads();
#pragma unroll
        for (int it = 0; it < 4; it++) {
            int idx = it * 256 + tid;
            int r = idx >> 4, hx = idx & 15;
            size_t go = ((size_t)kt * 64 + r) * 128 + hx * 8;
            *(uint4*)(sm + AK_H + r * 272 + hx * 16) = *(const uint4*)(khp + go);
        }
#pragma unroll
        for (int it = 0; it < 4; it++) {
            int idx = it * 256 + tid;
            int r = idx >> 3, hx = idx & 7;
            size_t go = (size_t)r * Tn + kt * 64 + hx * 8;
            *(uint4*)(sm + AV_H + r * 144 + hx * 16) = *(const uint4*)(vhp + go);
        }
        __syncthreads();

        // ---- S = (Qh + Ql) Kh^T, f32 acc ----
        float s[8][4];
#pragma unroll
        for (int i = 0; i < 8; i++)
#pragma unroll
            for (int j = 0; j < 4; j++) s[i][j] = 0.f;

#pragma unroll
        for (int kk = 0; kk < 8; kk++) {
            uint32_t qah[4], qal[4];
            ldsm4(qah, qbase + kk * 32);
            ldsm4(qal, qbase + (AQ_L - AQ_H) + kk * 32);
            uint32_t kb[8][2];
#pragma unroll
            for (int p = 0; p < 4; p++)
                ldsm4(&kb[2 * p][0], kbase + p * (16 * 272) + kk * 32);
#pragma unroll
            for (int nt = 0; nt < 8; nt++) mma_f32a(s[nt], qah, kb[nt]);
#pragma unroll
            for (int nt = 0; nt < 8; nt++) mma_f32a(s[nt], qal, kb[nt]);
        }

        // ---- online softmax (2 rows per lane: lg, lg+8) ----
        float mx0 = s[0][0], mx1 = s[0][2];
#pragma unroll
        for (int nt = 0; nt < 8; nt++) {
            mx0 = fmaxf(mx0, fmaxf(s[nt][0], s[nt][1]));
            mx1 = fmaxf(mx1, fmaxf(s[nt][2], s[nt][3]));
        }
        mx0 = fmaxf(mx0, __shfl_xor_sync(0xffffffffu, mx0, 1));
        mx0 = fmaxf(mx0, __shfl_xor_sync(0xffffffffu, mx0, 2));
        mx1 = fmaxf(mx1, __shfl_xor_sync(0xffffffffu, mx1, 1));
        mx1 = fmaxf(mx1, __shfl_xor_sync(0xffffffffu, mx1, 2));
        float mn0 = fmaxf(m0, mx0), mn1 = fmaxf(m1, mx1);
        float cr0 = ex2f(m0 - mn0), cr1 = ex2f(m1 - mn1);
        m0 = mn0; m1 = mn1;
        float sum0 = 0.f, sum1 = 0.f;
#pragma unroll
        for (int nt = 0; nt < 8; nt++) {
            s[nt][0] = ex2f(s[nt][0] - mn0);
            s[nt][1] = ex2f(s[nt][1] - mn0);
            s[nt][2] = ex2f(s[nt][2] - mn1);
            s[nt][3] = ex2f(s[nt][3] - mn1);
            sum0 += s[nt][0] + s[nt][1];
            sum1 += s[nt][2] + s[nt][3];
        }
        sum0 += __shfl_xor_sync(0xffffffffu, sum0, 1);
        sum0 += __shfl_xor_sync(0xffffffffu, sum0, 2);
        sum1 += __shfl_xor_sync(0xffffffffu, sum1, 1);
        sum1 += __shfl_xor_sync(0xffffffffu, sum1, 2);
        l0 = l0 * cr0 + sum0;
        l1 = l1 * cr1 + sum1;
#pragma unroll
        for (int nt = 0; nt < 16; nt++) {
            o[nt][0] *= cr0; o[nt][1] *= cr0;
            o[nt][2] *= cr1; o[nt][3] *= cr1;
        }

        // ---- O += (Ph + Pl) Vh, f32 acc ----
#pragma unroll
        for (int kk = 0; kk < 4; kk++) {
            uint32_t ph[4], pl[4];
#pragma unroll
            for (int q2 = 0; q2 < 2; q2++) {
                float e0 = s[2 * kk + q2][0], e1 = s[2 * kk + q2][1];
                ph[2 * q2] = pkh2(e0, e1);
                float2 hp = uph2(ph[2 * q2]);
                pl[2 * q2] = pkh2(e0 - hp.x, e1 - hp.y);
                e0 = s[2 * kk + q2][2]; e1 = s[2 * kk + q2][3];
                ph[2 * q2 + 1] = pkh2(e0, e1);
                hp = uph2(ph[2 * q2 + 1]);
                pl[2 * q2 + 1] = pkh2(e0 - hp.x, e1 - hp.y);
            }
#pragma unroll
            for (int blk = 0; blk < 2; blk++) {
                uint32_t vb[8][2];
#pragma unroll
                for (int p = 0; p < 4; p++)
                    ldsm4(&vb[2 * p][0], vbase + (blk * 64 + p * 16) * 144 + kk * 32);
#pragma unroll
                for (int j = 0; j < 8; j++) mma_f32a(o[blk * 8 + j], ph, vb[j]);
#pragma unroll
                for (int j = 0; j < 8; j++) mma_f32a(o[blk * 8 + j], pl, vb[j]);
            }
        }
    }

    // ---- epilogue: y = O / l, split to f16 hi/lo ----
    float i0 = 1.f / l0, i1 = 1.f / l1;
    size_t row0 = (size_t)b * Tn + qb * 128 + wid * 16 + lg;
#pragma unroll
    for (int nt = 0; nt < 16; nt++) {
        int col = h * 128 + nt * 8 + tq * 2;
        float v0 = o[nt][0] * i0, v1 = o[nt][1] * i0;
        uint32_t hh = pkh2(v0, v1);
        float2 hp = uph2(hh);
        *(uint32_t*)(g_yh + row0 * Cn + col) = hh;
        *(uint32_t*)(g_yl + row0 * Cn + col) = pkh2(v0 - hp.x, v1 - hp.y);
        v0 = o[nt][2] * i1; v1 = o[nt][3] * i1;
        hh = pkh2(v0, v1);
        hp = uph2(hh);
        *(uint32_t*)(g_yh + (row0 + 8) * Cn + col) = hh;
        *(uint32_t*)(g_yl + (row0 + 8) * Cn + col) = pkh2(v0 - hp.x, v1 - hp.y);
    }
}

// ---------------------------------------------------------------------------
extern "C" void kernel_launch(void* const* d_in, const int* in_sizes, int n_in,
                              void* d_out, int out_size) {
    const float* x      = (const float*)d_in[0];
    const float* cosb   = (const float*)d_in[1];
    const float* sinb   = (const float*)d_in[2];
    const float* w_attn = (const float*)d_in[3];
    const float* w_proj = (const float*)d_in[4];
    float* out = (float*)d_out;
    (void)in_sizes; (void)n_in; (void)out_size;

    (void)cudaFuncSetAttribute(hgemm2_kernel,
                               cudaFuncAttributeMaxDynamicSharedMemorySize, GSM);
    (void)cudaFuncSetAttribute(attn_kernel,
                               cudaFuncAttributeMaxDynamicSharedMemorySize, ATT_SMEM);

    float* qkvp = nullptr;
    f16 *xh, *xl, *wah, *wph, *yh, *yl;
    (void)cudaGetSymbolAddress((void**)&qkvp, g_qkv);
    (void)cudaGetSymbolAddress((void**)&xh, g_xh);
    (void)cudaGetSymbolAddress((void**)&xl, g_xl);
    (void)cudaGetSymbolAddress((void**)&wah, g_wah);
    (void)cudaGetSymbolAddress((void**)&wph, g_wph);
    (void)cudaGetSymbolAddress((void**)&yh, g_yh);
    (void)cudaGetSymbolAddress((void**)&yl, g_yl);

    // 0. splits (weights: fp16 hi only)
    splitx_kernel<<<(ROWS * GK / 4) / 256, 256>>>(x);
    wsplit_kernel<<<dim3(QKVW / 32, GK / 32), dim3(32, 8)>>>(w_attn, wah, QKVW);
    wsplit_kernel<<<dim3(Cn / 32, GK / 32), dim3(32, 8)>>>(w_proj, wph, Cn);
    // 1. qkv = x @ w_attn (2-term)
    hgemm2_kernel<<<dim3(QKVW / 128, ROWS / 64), 256, GSM>>>(xh, xl, wah, qkvp, QKVW);
    // 2. RoPE + split q (hi/lo), k (hi)
    rope_split_kernel<<<(ROWS * 4 * 5 * 64) / 256, 256>>>(cosb, sinb);
    // 3. v transpose (hi)
    vsplit_kernel<<<dim3(Tn / 32, 4, 8), dim3(32, 8)>>>();
    // 4. attention -> yh/yl
    attn_kernel<<<dim3(Tn / 128, 16, 2), 256, ATT_SMEM>>>();
    // 5. out = y @ w_proj (2-term)
    hgemm2_kernel<<<dim3(Cn / 128, ROWS / 64), 256, GSM>>>(yh, yl, wph, out, Cn);
}

// round 10
// speedup vs baseline: 1.7326x; 1.1462x over previous
#include <cuda_runtime.h>
#include <cuda_fp16.h>
#include <cstdint>
#include <cstddef>

// ---------------------------------------------------------------------------
// SelfAttention on sm_103, mma.sync fp16 multi-term.
// R10: attention goes 1-term (plain fp16 Q,K,V,P with f32 accumulate) --
// adds Q-rounding and P-rounding noise sources (~2e-4 each, calibrated in
// R8/R9), predicted total ~5.8e-4 vs 1e-3 gate. Attention MMA count halves.
// GEMMs stay 2-term (x = xh + xl vs fp16 weights); y stays hi/lo into gemm2.
// ---------------------------------------------------------------------------

#define Tn     2048
#define Cn     2048
#define QKVW   3072          // (16 + 2*4) * 128
#define ROWS   4096          // B*T
#define GK     2048          // K dim of both big GEMMs

typedef __half f16;

__device__ __align__(16) float g_qkv[(size_t)ROWS * QKVW];
__device__ __align__(16) f16  g_xh[(size_t)ROWS * GK];
__device__ __align__(16) f16  g_xl[(size_t)ROWS * GK];
__device__ __align__(16) f16  g_wah[(size_t)QKVW * GK];
__device__ __align__(16) f16  g_wph[(size_t)Cn * GK];
__device__ __align__(16) f16  g_qh[(size_t)2 * 16 * Tn * 128];
__device__ __align__(16) f16  g_kh[(size_t)2 * 4 * Tn * 128];
__device__ __align__(16) f16  g_vth[(size_t)2 * 4 * 128 * Tn];
__device__ __align__(16) f16  g_yh[(size_t)ROWS * Cn];
__device__ __align__(16) f16  g_yl[(size_t)ROWS * Cn];

// 1/sqrt(128) * log2(e): softmax scale + exp->exp2, folded into q
#define QK_SCALE (0.08838834764831845f * 1.4426950408889634f)

// ============================ helpers =======================================
__device__ __forceinline__ float ex2f(float x) {
    float r;
    asm("ex2.approx.ftz.f32 %0, %1;" : "=f"(r) : "f"(x));
    return r;
}
__device__ __forceinline__ uint32_t pkh2(float lo, float hi) {
    __half2 h = __floats2half2_rn(lo, hi);
    return *reinterpret_cast<uint32_t*>(&h);
}
__device__ __forceinline__ float2 uph2(uint32_t u) {
    __half2 h = *reinterpret_cast<__half2*>(&u);
    return __half22float2(h);
}
__device__ __forceinline__ void mma_f32a(float (&d)[4], const uint32_t (&a)[4],
                                         const uint32_t* b) {
    asm volatile(
        "mma.sync.aligned.m16n8k16.row.col.f32.f16.f16.f32 "
        "{%0,%1,%2,%3}, {%4,%5,%6,%7}, {%8,%9}, {%0,%1,%2,%3};"
        : "+f"(d[0]), "+f"(d[1]), "+f"(d[2]), "+f"(d[3])
        : "r"(a[0]), "r"(a[1]), "r"(a[2]), "r"(a[3]), "r"(b[0]), "r"(b[1]));
}
__device__ __forceinline__ void ldsm4(uint32_t* r, uint32_t a) {
    asm volatile("ldmatrix.sync.aligned.m8n8.x4.shared.b16 {%0,%1,%2,%3}, [%4];"
                 : "=r"(r[0]), "=r"(r[1]), "=r"(r[2]), "=r"(r[3]) : "r"(a));
}
__device__ __forceinline__ uint32_t smem_u32(const void* p) {
    uint32_t a;
    asm("{ .reg .u64 t; cvta.to.shared.u64 t, %1; cvt.u32.u64 %0, t; }"
        : "=r"(a) : "l"(p));
    return a;
}
#define CP16(dst, src) \
    asm volatile("cp.async.cg.shared.global [%0], [%1], 16;" \
                 :: "r"(dst), "l"(src) : "memory")
#define CPCOMMIT() asm volatile("cp.async.commit_group;" ::: "memory")
#define CPWAIT1()  asm volatile("cp.async.wait_group 1;" ::: "memory")
#define CPWAIT0()  asm volatile("cp.async.wait_group 0;" ::: "memory")

// ---------------------------------------------------------------------------
// split x -> f16 hi/lo
// ---------------------------------------------------------------------------
__global__ __launch_bounds__(256) void splitx_kernel(const float* __restrict__ x) {
    size_t i = ((size_t)blockIdx.x * 256 + threadIdx.x) * 4;
    float4 v = *(const float4*)(x + i);
    f16 h0 = __float2half_rn(v.x), h1 = __float2half_rn(v.y);
    f16 h2 = __float2half_rn(v.z), h3 = __float2half_rn(v.w);
    f16 l0 = __float2half_rn(v.x - __half2float(h0));
    f16 l1 = __float2half_rn(v.y - __half2float(h1));
    f16 l2 = __float2half_rn(v.z - __half2float(h2));
    f16 l3 = __float2half_rn(v.w - __half2float(h3));
    g_xh[i] = h0; g_xh[i + 1] = h1; g_xh[i + 2] = h2; g_xh[i + 3] = h3;
    g_xl[i] = l0; g_xl[i + 1] = l1; g_xl[i + 2] = l2; g_xl[i + 3] = l3;
}

// ---------------------------------------------------------------------------
// transpose weights to fp16 (hi only): in [2048][Ccols] fp32 -> [Ccols][2048]
// ---------------------------------------------------------------------------
__global__ __launch_bounds__(256) void wsplit_kernel(
    const float* __restrict__ in, f16* __restrict__ hi, int Ccols)
{
    __shared__ float tb[32][33];
    const int bx = blockIdx.x * 32, by = blockIdx.y * 32;
    const int tx = threadIdx.x, ty = threadIdx.y;
#pragma unroll
    for (int j = 0; j < 32; j += 8)
        tb[ty + j][tx] = in[(size_t)(by + ty + j) * Ccols + bx + tx];
    __syncthreads();
#pragma unroll
    for (int j = 0; j < 32; j += 8) {
        float v = tb[tx][ty + j];
        hi[(size_t)(bx + ty + j) * GK + by + tx] = __float2half_rn(v);
    }
}

// ---------------------------------------------------------------------------
// fp16 2-term GEMM: C[M,N] = (Ah + Al) @ Bh^T, f32 accumulate.
// CTA tile 64x128, kchunk 32, cp.async double buffer, 8 warps (2m x 4n).
// ---------------------------------------------------------------------------
#define GS_STAGE 20480
#define GSM (2 * GS_STAGE)

__global__ __launch_bounds__(256, 2) void hgemm2_kernel(
    const f16* __restrict__ Ah, const f16* __restrict__ Al,
    const f16* __restrict__ Bh,
    float* __restrict__ C, int N)
{
    extern __shared__ char sm[];
    const uint32_t sb = smem_u32(sm);
    const int tid = threadIdx.x;
    const int lane = tid & 31, wid = tid >> 5;
    const int lg = lane >> 2, tq = lane & 3;
    const int mi = wid & 1, ni = wid >> 1;
    const size_t m0 = (size_t)blockIdx.y * 64, n0 = (size_t)blockIdx.x * 128;

    const uint32_t abase =
        (uint32_t)((mi * 32 + (lane & 15)) * 80 + (lane >> 4) * 16);
    const uint32_t bbase =
        (uint32_t)(10240 + (ni * 32 + (lane & 7) + ((lane >> 4) * 8)) * 80 +
                   ((lane >> 3) & 1) * 16);

    const int ar = tid >> 2;
    const int ac = tid & 3;
    const f16* pAh = Ah + (m0 + ar) * GK + ac * 8;
    const f16* pAl = Al + (m0 + ar) * GK + ac * 8;
    const f16* pBh = Bh + (n0 + ar) * GK + ac * 8;
    const uint32_t sdA = sb + ar * 80 + ac * 16;
    const uint32_t sdB = sb + 10240 + ar * 80 + ac * 16;

    float c[2][4][4];
#pragma unroll
    for (int a = 0; a < 2; a++)
#pragma unroll
        for (int b = 0; b < 4; b++)
#pragma unroll
            for (int d = 0; d < 4; d++) c[a][b][d] = 0.f;

    {
        CP16(sdA,         pAh);
        CP16(sdA + 5120,  pAl);
        CP16(sdB,           pBh);
        CP16(sdB + 64 * 80, pBh + (size_t)64 * GK);
        CPCOMMIT();
    }

#pragma unroll 1
    for (int kt = 0; kt < GK / 32; kt++) {
        const int s = kt & 1;
        if (kt + 1 < GK / 32) {
            uint32_t dA = sdA + (s ^ 1) * GS_STAGE;
            uint32_t dB = sdB + (s ^ 1) * GS_STAGE;
            size_t off = (size_t)(kt + 1) * 32;
            CP16(dA,         pAh + off);
            CP16(dA + 5120,  pAl + off);
            CP16(dB,           pBh + off);
            CP16(dB + 64 * 80, pBh + off + (size_t)64 * GK);
            CPCOMMIT();
            CPWAIT1();
        } else {
            CPWAIT0();
        }
        __syncthreads();

        const uint32_t stg = sb + s * GS_STAGE;
#pragma unroll
        for (int kk = 0; kk < 2; kk++) {
            uint32_t ah[2][4], al[2][4];
#pragma unroll
            for (int mt = 0; mt < 2; mt++) {
                uint32_t aa = stg + abase + mt * (16 * 80) + kk * 32;
                ldsm4(ah[mt], aa);
                ldsm4(al[mt], aa + 5120);
            }
            uint32_t bb[4][2];
#pragma unroll
            for (int p = 0; p < 2; p++)
                ldsm4(&bb[2 * p][0], stg + bbase + p * (16 * 80) + kk * 32);
#pragma unroll
            for (int mt = 0; mt < 2; mt++)
#pragma unroll
                for (int nt = 0; nt < 4; nt++) mma_f32a(c[mt][nt], ah[mt], bb[nt]);
#pragma unroll
            for (int mt = 0; mt < 2; mt++)
#pragma unroll
                for (int nt = 0; nt < 4; nt++) mma_f32a(c[mt][nt], al[mt], bb[nt]);
        }
        __syncthreads();
    }

#pragma unroll
    for (int mt = 0; mt < 2; mt++) {
        size_t r0 = m0 + mi * 32 + mt * 16 + lg;
#pragma unroll
        for (int nt = 0; nt < 4; nt++) {
            size_t col = n0 + ni * 32 + nt * 8 + tq * 2;
            *(float2*)(C + r0 * N + col) = make_float2(c[mt][nt][0], c[mt][nt][1]);
            *(float2*)(C + (r0 + 8) * N + col) = make_float2(c[mt][nt][2], c[mt][nt][3]);
        }
    }
}

// ---------------------------------------------------------------------------
// RoPE + fp16: q (slots 0-3, scaled) -> g_qh; k (slot 4) -> g_kh
// ---------------------------------------------------------------------------
__global__ __launch_bounds__(256) void rope_split_kernel(
    const float* __restrict__ cosb, const float* __restrict__ sinb)
{
    int idx = blockIdx.x * 256 + threadIdx.x;     // ROWS*4*5*64
    int d = idx & 63;
    int rg = idx >> 6;
    int slot = rg % 5;
    int q5 = rg / 5;
    int grp = q5 & 3;
    int row = q5 >> 2;
    int b = row >> 11, t = row & (Tn - 1);

    const float* p = g_qkv + (size_t)row * QKVW + grp * 768 + slot * 128 + d;
    float x1 = p[0], x2 = p[64];
    float cc = cosb[t * 64 + d], ss = sinb[t * 64 + d];
    float o1 = x1 * cc - x2 * ss;
    float o2 = x1 * ss + x2 * cc;

    if (slot < 4) {
        o1 *= QK_SCALE; o2 *= QK_SCALE;
        int head = grp * 4 + slot;
        size_t base = ((size_t)(b * 16 + head) * Tn + t) * 128 + d;
        g_qh[base]      = __float2half_rn(o1);
        g_qh[base + 64] = __float2half_rn(o2);
    } else {
        size_t base = ((size_t)(b * 4 + grp) * Tn + t) * 128 + d;
        g_kh[base]      = __float2half_rn(o1);
        g_kh[base + 64] = __float2half_rn(o2);
    }
}

// ---------------------------------------------------------------------------
// v: transpose -> g_vth [b][g][d][t]
// ---------------------------------------------------------------------------
__global__ __launch_bounds__(256) void vsplit_kernel() {
    __shared__ float tb[32][33];
    const int bg = blockIdx.z;
    const int t0 = blockIdx.x * 32, d0 = blockIdx.y * 32;
    const int tx = threadIdx.x, ty = threadIdx.y;
    const int b = bg >> 2, grp = bg & 3;
#pragma unroll
    for (int j = 0; j < 32; j += 8)
        tb[ty + j][tx] = g_qkv[((size_t)b * Tn + t0 + ty + j) * QKVW +
                               grp * 768 + 640 + d0 + tx];
    __syncthreads();
#pragma unroll
    for (int j = 0; j < 32; j += 8) {
        float v = tb[tx][ty + j];
        size_t o = ((size_t)bg * 128 + d0 + ty + j) * Tn + t0 + tx;
        g_vth[o] = __float2half_rn(v);
    }
}

// ---------------------------------------------------------------------------
// Flash attention, plain fp16 inputs, f32 accumulate (1-term S and PV).
// CTA = (qb, h, b): 128 q rows, 8 warps x m16. Key tiles of 64.
// smem: Qh [128 x 272B], Kh [64 x 272B], Vth [128 d x 144B] = 70656 B.
// ---------------------------------------------------------------------------
#define AQ_H 0
#define AK_H 34816
#define AV_H 52224
#define ATT_SMEM 70656

__global__ __launch_bounds__(256, 1) void attn_kernel() {
    extern __shared__ char sm[];
    const uint32_t sb = smem_u32(sm);
    const int tid = threadIdx.x;
    const int lane = tid & 31, wid = tid >> 5;
    const int lg = lane >> 2, tq = lane & 3;
    const int qb = blockIdx.x, h = blockIdx.y, b = blockIdx.z;
    const int grp = h >> 2;

    const uint32_t qbase = sb + AQ_H + (wid * 16 + (lane & 15)) * 272 +
                           (lane >> 4) * 16;
    const uint32_t kbase = sb + AK_H + ((lane & 7) + ((lane >> 4) * 8)) * 272 +
                           ((lane >> 3) & 1) * 16;
    const uint32_t vbase = sb + AV_H + ((lane & 7) + ((lane >> 4) * 8)) * 144 +
                           ((lane >> 3) & 1) * 16;

    // load Q, 128 x 128 f16
    {
        const f16* qhp = g_qh + ((size_t)(b * 16 + h) * Tn + qb * 128) * 128;
#pragma unroll
        for (int it = 0; it < 8; it++) {
            int idx = it * 256 + tid;
            int r = idx >> 4, hx = idx & 15;
            *(uint4*)(sm + AQ_H + r * 272 + hx * 16) =
                *(const uint4*)(qhp + (size_t)r * 128 + hx * 8);
        }
    }

    float o[16][4];
#pragma unroll
    for (int i = 0; i < 16; i++)
#pragma unroll
        for (int j = 0; j < 4; j++) o[i][j] = 0.f;
    float m0 = __int_as_float(0xff800000), m1 = m0;
    float l0 = 0.f, l1 = 0.f;

    const f16* khp = g_kh + (size_t)(b * 4 + grp) * Tn * 128;
    const f16* vhp = g_vth + (size_t)(b * 4 + grp) * 128 * Tn;

#pragma unroll 1
    for (int kt = 0; kt < Tn / 64; kt++) {
        __syncthreads();
#pragma unroll
        for (int it = 0; it < 4; it++) {
            int idx = it * 256 + tid;
            int r = idx >> 4, hx = idx & 15;
            size_t go = ((size_t)kt * 64 + r) * 128 + hx * 8;
            *(uint4*)(sm + AK_H + r * 272 + hx * 16) = *(const uint4*)(khp + go);
        }
#pragma unroll
        for (int it = 0; it < 4; it++) {
            int idx = it * 256 + tid;
            int r = idx >> 3, hx = idx & 7;
            size_t go = (size_t)r * Tn + kt * 64 + hx * 8;
            *(uint4*)(sm + AV_H + r * 144 + hx * 16) = *(const uint4*)(vhp + go);
        }
        __syncthreads();

        // ---- S = Q Kh^T, f32 acc ----
        float s[8][4];
#pragma unroll
        for (int i = 0; i < 8; i++)
#pragma unroll
            for (int j = 0; j < 4; j++) s[i][j] = 0.f;

#pragma unroll
        for (int kk = 0; kk < 8; kk++) {
            uint32_t qah[4];
            ldsm4(qah, qbase + kk * 32);
            uint32_t kb[8][2];
#pragma unroll
            for (int p = 0; p < 4; p++)
                ldsm4(&kb[2 * p][0], kbase + p * (16 * 272) + kk * 32);
#pragma unroll
            for (int nt = 0; nt < 8; nt++) mma_f32a(s[nt], qah, kb[nt]);
        }

        // ---- online softmax (2 rows per lane: lg, lg+8) ----
        float mx0 = s[0][0], mx1 = s[0][2];
#pragma unroll
        for (int nt = 0; nt < 8; nt++) {
            mx0 = fmaxf(mx0, fmaxf(s[nt][0], s[nt][1]));
            mx1 = fmaxf(mx1, fmaxf(s[nt][2], s[nt][3]));
        }
        mx0 = fmaxf(mx0, __shfl_xor_sync(0xffffffffu, mx0, 1));
        mx0 = fmaxf(mx0, __shfl_xor_sync(0xffffffffu, mx0, 2));
        mx1 = fmaxf(mx1, __shfl_xor_sync(0xffffffffu, mx1, 1));
        mx1 = fmaxf(mx1, __shfl_xor_sync(0xffffffffu, mx1, 2));
        float mn0 = fmaxf(m0, mx0), mn1 = fmaxf(m1, mx1);
        float cr0 = ex2f(m0 - mn0), cr1 = ex2f(m1 - mn1);
        m0 = mn0; m1 = mn1;
        float sum0 = 0.f, sum1 = 0.f;
#pragma unroll
        for (int nt = 0; nt < 8; nt++) {
            s[nt][0] = ex2f(s[nt][0] - mn0);
            s[nt][1] = ex2f(s[nt][1] - mn0);
            s[nt][2] = ex2f(s[nt][2] - mn1);
            s[nt][3] = ex2f(s[nt][3] - mn1);
            sum0 += s[nt][0] + s[nt][1];
            sum1 += s[nt][2] + s[nt][3];
        }
        sum0 += __shfl_xor_sync(0xffffffffu, sum0, 1);
        sum0 += __shfl_xor_sync(0xffffffffu, sum0, 2);
        sum1 += __shfl_xor_sync(0xffffffffu, sum1, 1);
        sum1 += __shfl_xor_sync(0xffffffffu, sum1, 2);
        l0 = l0 * cr0 + sum0;
        l1 = l1 * cr1 + sum1;
#pragma unroll
        for (int nt = 0; nt < 16; nt++) {
            o[nt][0] *= cr0; o[nt][1] *= cr0;
            o[nt][2] *= cr1; o[nt][3] *= cr1;
        }

        // ---- O += Ph Vh, f32 acc ----
#pragma unroll
        for (int kk = 0; kk < 4; kk++) {
            uint32_t ph[4];
#pragma unroll
            for (int q2 = 0; q2 < 2; q2++) {
                ph[2 * q2]     = pkh2(s[2 * kk + q2][0], s[2 * kk + q2][1]);
                ph[2 * q2 + 1] = pkh2(s[2 * kk + q2][2], s[2 * kk + q2][3]);
            }
#pragma unroll
            for (int blk = 0; blk < 2; blk++) {
                uint32_t vb[8][2];
#pragma unroll
                for (int p = 0; p < 4; p++)
                    ldsm4(&vb[2 * p][0], vbase + (blk * 64 + p * 16) * 144 + kk * 32);
#pragma unroll
                for (int j = 0; j < 8; j++) mma_f32a(o[blk * 8 + j], ph, vb[j]);
            }
        }
    }

    // ---- epilogue: y = O / l, split to f16 hi/lo ----
    float i0 = 1.f / l0, i1 = 1.f / l1;
    size_t row0 = (size_t)b * Tn + qb * 128 + wid * 16 + lg;
#pragma unroll
    for (int nt = 0; nt < 16; nt++) {
        int col = h * 128 + nt * 8 + tq * 2;
        float v0 = o[nt][0] * i0, v1 = o[nt][1] * i0;
        uint32_t hh = pkh2(v0, v1);
        float2 hp = uph2(hh);
        *(uint32_t*)(g_yh + row0 * Cn + col) = hh;
        *(uint32_t*)(g_yl + row0 * Cn + col) = pkh2(v0 - hp.x, v1 - hp.y);
        v0 = o[nt][2] * i1; v1 = o[nt][3] * i1;
        hh = pkh2(v0, v1);
        hp = uph2(hh);
        *(uint32_t*)(g_yh + (row0 + 8) * Cn + col) = hh;
        *(uint32_t*)(g_yl + (row0 + 8) * Cn + col) = pkh2(v0 - hp.x, v1 - hp.y);
    }
}

// ---------------------------------------------------------------------------
extern "C" void kernel_launch(void* const* d_in, const int* in_sizes, int n_in,
                              void* d_out, int out_size) {
    const float* x      = (const float*)d_in[0];
    const float* cosb   = (const float*)d_in[1];
    const float* sinb   = (const float*)d_in[2];
    const float* w_attn = (const float*)d_in[3];
    const float* w_proj = (const float*)d_in[4];
    float* out = (float*)d_out;
    (void)in_sizes; (void)n_in; (void)out_size;

    (void)cudaFuncSetAttribute(hgemm2_kernel,
                               cudaFuncAttributeMaxDynamicSharedMemorySize, GSM);
    (void)cudaFuncSetAttribute(attn_kernel,
                               cudaFuncAttributeMaxDynamicSharedMemorySize, ATT_SMEM);

    float* qkvp = nullptr;
    f16 *xh, *xl, *wah, *wph, *yh, *yl;
    (void)cudaGetSymbolAddress((void**)&qkvp, g_qkv);
    (void)cudaGetSymbolAddress((void**)&xh, g_xh);
    (void)cudaGetSymbolAddress((void**)&xl, g_xl);
    (void)cudaGetSymbolAddress((void**)&wah, g_wah);
    (void)cudaGetSymbolAddress((void**)&wph, g_wph);
    (void)cudaGetSymbolAddress((void**)&yh, g_yh);
    (void)cudaGetSymbolAddress((void**)&yl, g_yl);

    // 0. splits (weights: fp16)
    splitx_kernel<<<(ROWS * GK / 4) / 256, 256>>>(x);
    wsplit_kernel<<<dim3(QKVW / 32, GK / 32), dim3(32, 8)>>>(w_attn, wah, QKVW);
    wsplit_kernel<<<dim3(Cn / 32, GK / 32), dim3(32, 8)>>>(w_proj, wph, Cn);
    // 1. qkv = x @ w_attn (2-term)
    hgemm2_kernel<<<dim3(QKVW / 128, ROWS / 64), 256, GSM>>>(xh, xl, wah, qkvp, QKVW);
    // 2. RoPE -> q, k (fp16)
    rope_split_kernel<<<(ROWS * 4 * 5 * 64) / 256, 256>>>(cosb, sinb);
    // 3. v transpose (fp16)
    vsplit_kernel<<<dim3(Tn / 32, 4, 8), dim3(32, 8)>>>();
    // 4. attention -> yh/yl
    attn_kernel<<<dim3(Tn / 128, 16, 2), 256, ATT_SMEM>>>();
    // 5. out = y @ w_proj (2-term)
    hgemm2_kernel<<<dim3(Cn / 128, ROWS / 64), 256, GSM>>>(yh, yl, wph, out, Cn);
}

// round 11
// speedup vs baseline: 2.2653x; 1.3074x over previous
#include <cuda_runtime.h>
#include <cuda_fp16.h>
#include <cstdint>
#include <cstddef>

// ---------------------------------------------------------------------------
// SelfAttention on sm_103, mma.sync fp16, fp32 accumulate everywhere.
// R11: 1-term GEMMs (pure fp16 operands). Error ledger (calibrated R8-R10):
//   attention operand roundings (K,V,Q,P)        ~5.8e-4 total so far
//   + x rounding (gemm1) ~2.9e-4, y rounding (gemm2) ~2.9e-4
//   => predicted ~7.1e-4 vs 1e-3 gate.
// All MMA kernels run at the sm_103 legacy-HMMA ceiling (512 MAC/cyc/SM);
// time scales purely with MMA count. Total tensor work now 77.4 G MAC.
// ---------------------------------------------------------------------------

#define Tn     2048
#define Cn     2048
#define QKVW   3072          // (16 + 2*4) * 128
#define ROWS   4096          // B*T
#define GK     2048          // K dim of both big GEMMs

typedef __half f16;

__device__ __align__(16) float g_qkv[(size_t)ROWS * QKVW];
__device__ __align__(16) f16  g_xh[(size_t)ROWS * GK];
__device__ __align__(16) f16  g_wah[(size_t)QKVW * GK];
__device__ __align__(16) f16  g_wph[(size_t)Cn * GK];
__device__ __align__(16) f16  g_qh[(size_t)2 * 16 * Tn * 128];
__device__ __align__(16) f16  g_kh[(size_t)2 * 4 * Tn * 128];
__device__ __align__(16) f16  g_vth[(size_t)2 * 4 * 128 * Tn];
__device__ __align__(16) f16  g_yh[(size_t)ROWS * Cn];

// 1/sqrt(128) * log2(e): softmax scale + exp->exp2, folded into q
#define QK_SCALE (0.08838834764831845f * 1.4426950408889634f)

// ============================ helpers =======================================
__device__ __forceinline__ float ex2f(float x) {
    float r;
    asm("ex2.approx.ftz.f32 %0, %1;" : "=f"(r) : "f"(x));
    return r;
}
__device__ __forceinline__ uint32_t pkh2(float lo, float hi) {
    __half2 h = __floats2half2_rn(lo, hi);
    return *reinterpret_cast<uint32_t*>(&h);
}
__device__ __forceinline__ void mma_f32a(float (&d)[4], const uint32_t (&a)[4],
                                         const uint32_t* b) {
    asm volatile(
        "mma.sync.aligned.m16n8k16.row.col.f32.f16.f16.f32 "
        "{%0,%1,%2,%3}, {%4,%5,%6,%7}, {%8,%9}, {%0,%1,%2,%3};"
        : "+f"(d[0]), "+f"(d[1]), "+f"(d[2]), "+f"(d[3])
        : "r"(a[0]), "r"(a[1]), "r"(a[2]), "r"(a[3]), "r"(b[0]), "r"(b[1]));
}
__device__ __forceinline__ void ldsm4(uint32_t* r, uint32_t a) {
    asm volatile("ldmatrix.sync.aligned.m8n8.x4.shared.b16 {%0,%1,%2,%3}, [%4];"
                 : "=r"(r[0]), "=r"(r[1]), "=r"(r[2]), "=r"(r[3]) : "r"(a));
}
__device__ __forceinline__ uint32_t smem_u32(const void* p) {
    uint32_t a;
    asm("{ .reg .u64 t; cvta.to.shared.u64 t, %1; cvt.u32.u64 %0, t; }"
        : "=r"(a) : "l"(p));
    return a;
}
#define CP16(dst, src) \
    asm volatile("cp.async.cg.shared.global [%0], [%1], 16;" \
                 :: "r"(dst), "l"(src) : "memory")
#define CPCOMMIT() asm volatile("cp.async.commit_group;" ::: "memory")
#define CPWAIT1()  asm volatile("cp.async.wait_group 1;" ::: "memory")
#define CPWAIT0()  asm volatile("cp.async.wait_group 0;" ::: "memory")

// ---------------------------------------------------------------------------
// convert x -> fp16
// ---------------------------------------------------------------------------
__global__ __launch_bounds__(256) void splitx_kernel(const float* __restrict__ x) {
    size_t i = ((size_t)blockIdx.x * 256 + threadIdx.x) * 4;
    float4 v = *(const float4*)(x + i);
    uint32_t p0 = pkh2(v.x, v.y), p1 = pkh2(v.z, v.w);
    *(uint2*)(g_xh + i) = make_uint2(p0, p1);
}

// ---------------------------------------------------------------------------
// transpose weights to fp16: in [2048][Ccols] fp32 -> [Ccols][2048]
// ---------------------------------------------------------------------------
__global__ __launch_bounds__(256) void wsplit_kernel(
    const float* __restrict__ in, f16* __restrict__ hi, int Ccols)
{
    __shared__ float tb[32][33];
    const int bx = blockIdx.x * 32, by = blockIdx.y * 32;
    const int tx = threadIdx.x, ty = threadIdx.y;
#pragma unroll
    for (int j = 0; j < 32; j += 8)
        tb[ty + j][tx] = in[(size_t)(by + ty + j) * Ccols + bx + tx];
    __syncthreads();
#pragma unroll
    for (int j = 0; j < 32; j += 8) {
        float v = tb[tx][ty + j];
        hi[(size_t)(bx + ty + j) * GK + by + tx] = __float2half_rn(v);
    }
}

// ---------------------------------------------------------------------------
// fp16 1-term GEMM: C[M,N] = A @ B^T, f32 accumulate.
// CTA tile 64x128, kchunk 32, cp.async double buffer, 8 warps (2m x 4n).
// smem stage: A@0 (64 rows x 80B = 5120), B@5120 (128 x 80B = 10240).
// ---------------------------------------------------------------------------
#define GS_STAGE 15360
#define GSM (2 * GS_STAGE)

__global__ __launch_bounds__(256, 2) void hgemm1_kernel(
    const f16* __restrict__ A, const f16* __restrict__ B,
    float* __restrict__ C, int N)
{
    extern __shared__ char sm[];
    const uint32_t sb = smem_u32(sm);
    const int tid = threadIdx.x;
    const int lane = tid & 31, wid = tid >> 5;
    const int lg = lane >> 2, tq = lane & 3;
    const int mi = wid & 1, ni = wid >> 1;
    const size_t m0 = (size_t)blockIdx.y * 64, n0 = (size_t)blockIdx.x * 128;

    const uint32_t abase =
        (uint32_t)((mi * 32 + (lane & 15)) * 80 + (lane >> 4) * 16);
    const uint32_t bbase =
        (uint32_t)(5120 + (ni * 32 + (lane & 7) + ((lane >> 4) * 8)) * 80 +
                   ((lane >> 3) & 1) * 16);

    const int ar = tid >> 2;
    const int ac = tid & 3;
    const f16* pA = A + (m0 + ar) * GK + ac * 8;
    const f16* pB = B + (n0 + ar) * GK + ac * 8;
    const uint32_t sdA = sb + ar * 80 + ac * 16;
    const uint32_t sdB = sb + 5120 + ar * 80 + ac * 16;

    float c[2][4][4];
#pragma unroll
    for (int a = 0; a < 2; a++)
#pragma unroll
        for (int b = 0; b < 4; b++)
#pragma unroll
            for (int d = 0; d < 4; d++) c[a][b][d] = 0.f;

    {
        CP16(sdA,           pA);
        CP16(sdB,           pB);
        CP16(sdB + 64 * 80, pB + (size_t)64 * GK);
        CPCOMMIT();
    }

#pragma unroll 1
    for (int kt = 0; kt < GK / 32; kt++) {
        const int s = kt & 1;
        if (kt + 1 < GK / 32) {
            uint32_t dA = sdA + (s ^ 1) * GS_STAGE;
            uint32_t dB = sdB + (s ^ 1) * GS_STAGE;
            size_t off = (size_t)(kt + 1) * 32;
            CP16(dA,           pA + off);
            CP16(dB,           pB + off);
            CP16(dB + 64 * 80, pB + off + (size_t)64 * GK);
            CPCOMMIT();
            CPWAIT1();
        } else {
            CPWAIT0();
        }
        __syncthreads();

        const uint32_t stg = sb + s * GS_STAGE;
#pragma unroll
        for (int kk = 0; kk < 2; kk++) {
            uint32_t ah[2][4];
#pragma unroll
            for (int mt = 0; mt < 2; mt++)
                ldsm4(ah[mt], stg + abase + mt * (16 * 80) + kk * 32);
            uint32_t bb[4][2];
#pragma unroll
            for (int p = 0; p < 2; p++)
                ldsm4(&bb[2 * p][0], stg + bbase + p * (16 * 80) + kk * 32);
#pragma unroll
            for (int mt = 0; mt < 2; mt++)
#pragma unroll
                for (int nt = 0; nt < 4; nt++) mma_f32a(c[mt][nt], ah[mt], bb[nt]);
        }
        __syncthreads();
    }

#pragma unroll
    for (int mt = 0; mt < 2; mt++) {
        size_t r0 = m0 + mi * 32 + mt * 16 + lg;
#pragma unroll
        for (int nt = 0; nt < 4; nt++) {
            size_t col = n0 + ni * 32 + nt * 8 + tq * 2;
            *(float2*)(C + r0 * N + col) = make_float2(c[mt][nt][0], c[mt][nt][1]);
            *(float2*)(C + (r0 + 8) * N + col) = make_float2(c[mt][nt][2], c[mt][nt][3]);
        }
    }
}

// ---------------------------------------------------------------------------
// RoPE + fp16: q (slots 0-3, scaled) -> g_qh; k (slot 4) -> g_kh
// ---------------------------------------------------------------------------
__global__ __launch_bounds__(256) void rope_split_kernel(
    const float* __restrict__ cosb, const float* __restrict__ sinb)
{
    int idx = blockIdx.x * 256 + threadIdx.x;     // ROWS*4*5*64
    int d = idx & 63;
    int rg = idx >> 6;
    int slot = rg % 5;
    int q5 = rg / 5;
    int grp = q5 & 3;
    int row = q5 >> 2;
    int b = row >> 11, t = row & (Tn - 1);

    const float* p = g_qkv + (size_t)row * QKVW + grp * 768 + slot * 128 + d;
    float x1 = p[0], x2 = p[64];
    float cc = cosb[t * 64 + d], ss = sinb[t * 64 + d];
    float o1 = x1 * cc - x2 * ss;
    float o2 = x1 * ss + x2 * cc;

    if (slot < 4) {
        o1 *= QK_SCALE; o2 *= QK_SCALE;
        int head = grp * 4 + slot;
        size_t base = ((size_t)(b * 16 + head) * Tn + t) * 128 + d;
        g_qh[base]      = __float2half_rn(o1);
        g_qh[base + 64] = __float2half_rn(o2);
    } else {
        size_t base = ((size_t)(b * 4 + grp) * Tn + t) * 128 + d;
        g_kh[base]      = __float2half_rn(o1);
        g_kh[base + 64] = __float2half_rn(o2);
    }
}

// ---------------------------------------------------------------------------
// v: transpose -> g_vth [b][g][d][t]
// ---------------------------------------------------------------------------
__global__ __launch_bounds__(256) void vsplit_kernel() {
    __shared__ float tb[32][33];
    const int bg = blockIdx.z;
    const int t0 = blockIdx.x * 32, d0 = blockIdx.y * 32;
    const int tx = threadIdx.x, ty = threadIdx.y;
    const int b = bg >> 2, grp = bg & 3;
#pragma unroll
    for (int j = 0; j < 32; j += 8)
        tb[ty + j][tx] = g_qkv[((size_t)b * Tn + t0 + ty + j) * QKVW +
                               grp * 768 + 640 + d0 + tx];
    __syncthreads();
#pragma unroll
    for (int j = 0; j < 32; j += 8) {
        float v = tb[tx][ty + j];
        size_t o = ((size_t)bg * 128 + d0 + ty + j) * Tn + t0 + tx;
        g_vth[o] = __float2half_rn(v);
    }
}

// ---------------------------------------------------------------------------
// Flash attention, plain fp16 inputs, f32 accumulate.
// CTA = (qb, h, b): 128 q rows, 8 warps x m16. Key tiles of 64.
// smem: Qh [128 x 272B], Kh [64 x 272B], Vth [128 d x 144B] = 70656 B.
// ---------------------------------------------------------------------------
#define AQ_H 0
#define AK_H 34816
#define AV_H 52224
#define ATT_SMEM 70656

__global__ __launch_bounds__(256, 1) void attn_kernel() {
    extern __shared__ char sm[];
    const uint32_t sb = smem_u32(sm);
    const int tid = threadIdx.x;
    const int lane = tid & 31, wid = tid >> 5;
    const int lg = lane >> 2, tq = lane & 3;
    const int qb = blockIdx.x, h = blockIdx.y, b = blockIdx.z;
    const int grp = h >> 2;

    const uint32_t qbase = sb + AQ_H + (wid * 16 + (lane & 15)) * 272 +
                           (lane >> 4) * 16;
    const uint32_t kbase = sb + AK_H + ((lane & 7) + ((lane >> 4) * 8)) * 272 +
                           ((lane >> 3) & 1) * 16;
    const uint32_t vbase = sb + AV_H + ((lane & 7) + ((lane >> 4) * 8)) * 144 +
                           ((lane >> 3) & 1) * 16;

    // load Q, 128 x 128 f16
    {
        const f16* qhp = g_qh + ((size_t)(b * 16 + h) * Tn + qb * 128) * 128;
#pragma unroll
        for (int it = 0; it < 8; it++) {
            int idx = it * 256 + tid;
            int r = idx >> 4, hx = idx & 15;
            *(uint4*)(sm + AQ_H + r * 272 + hx * 16) =
                *(const uint4*)(qhp + (size_t)r * 128 + hx * 8);
        }
    }

    float o[16][4];
#pragma unroll
    for (int i = 0; i < 16; i++)
#pragma unroll
        for (int j = 0; j < 4; j++) o[i][j] = 0.f;
    float m0 = __int_as_float(0xff800000), m1 = m0;
    float l0 = 0.f, l1 = 0.f;

    const f16* khp = g_kh + (size_t)(b * 4 + grp) * Tn * 128;
    const f16* vhp = g_vth + (size_t)(b * 4 + grp) * 128 * Tn;

#pragma unroll 1
    for (int kt = 0; kt < Tn / 64; kt++) {
        __syncthreads();
#pragma unroll
        for (int it = 0; it < 4; it++) {
            int idx = it * 256 + tid;
            int r = idx >> 4, hx = idx & 15;
            size_t go = ((size_t)kt * 64 + r) * 128 + hx * 8;
            *(uint4*)(sm + AK_H + r * 272 + hx * 16) = *(const uint4*)(khp + go);
        }
#pragma unroll
        for (int it = 0; it < 4; it++) {
            int idx = it * 256 + tid;
            int r = idx >> 3, hx = idx & 7;
            size_t go = (size_t)r * Tn + kt * 64 + hx * 8;
            *(uint4*)(sm + AV_H + r * 144 + hx * 16) = *(const uint4*)(vhp + go);
        }
        __syncthreads();

        // ---- S = Q Kh^T, f32 acc ----
        float s[8][4];
#pragma unroll
        for (int i = 0; i < 8; i++)
#pragma unroll
            for (int j = 0; j < 4; j++) s[i][j] = 0.f;

#pragma unroll
        for (int kk = 0; kk < 8; kk++) {
            uint32_t qah[4];
            ldsm4(qah, qbase + kk * 32);
            uint32_t kb[8][2];
#pragma unroll
            for (int p = 0; p < 4; p++)
                ldsm4(&kb[2 * p][0], kbase + p * (16 * 272) + kk * 32);
#pragma unroll
            for (int nt = 0; nt < 8; nt++) mma_f32a(s[nt], qah, kb[nt]);
        }

        // ---- online softmax (2 rows per lane: lg, lg+8) ----
        float mx0 = s[0][0], mx1 = s[0][2];
#pragma unroll
        for (int nt = 0; nt < 8; nt++) {
            mx0 = fmaxf(mx0, fmaxf(s[nt][0], s[nt][1]));
            mx1 = fmaxf(mx1, fmaxf(s[nt][2], s[nt][3]));
        }
        mx0 = fmaxf(mx0, __shfl_xor_sync(0xffffffffu, mx0, 1));
        mx0 = fmaxf(mx0, __shfl_xor_sync(0xffffffffu, mx0, 2));
        mx1 = fmaxf(mx1, __shfl_xor_sync(0xffffffffu, mx1, 1));
        mx1 = fmaxf(mx1, __shfl_xor_sync(0xffffffffu, mx1, 2));
        float mn0 = fmaxf(m0, mx0), mn1 = fmaxf(m1, mx1);
        float cr0 = ex2f(m0 - mn0), cr1 = ex2f(m1 - mn1);
        m0 = mn0; m1 = mn1;
        float sum0 = 0.f, sum1 = 0.f;
#pragma unroll
        for (int nt = 0; nt < 8; nt++) {
            s[nt][0] = ex2f(s[nt][0] - mn0);
            s[nt][1] = ex2f(s[nt][1] - mn0);
            s[nt][2] = ex2f(s[nt][2] - mn1);
            s[nt][3] = ex2f(s[nt][3] - mn1);
            sum0 += s[nt][0] + s[nt][1];
            sum1 += s[nt][2] + s[nt][3];
        }
        sum0 += __shfl_xor_sync(0xffffffffu, sum0, 1);
        sum0 += __shfl_xor_sync(0xffffffffu, sum0, 2);
        sum1 += __shfl_xor_sync(0xffffffffu, sum1, 1);
        sum1 += __shfl_xor_sync(0xffffffffu, sum1, 2);
        l0 = l0 * cr0 + sum0;
        l1 = l1 * cr1 + sum1;
#pragma unroll
        for (int nt = 0; nt < 16; nt++) {
            o[nt][0] *= cr0; o[nt][1] *= cr0;
            o[nt][2] *= cr1; o[nt][3] *= cr1;
        }

        // ---- O += Ph Vh, f32 acc ----
#pragma unroll
        for (int kk = 0; kk < 4; kk++) {
            uint32_t ph[4];
#pragma unroll
            for (int q2 = 0; q2 < 2; q2++) {
                ph[2 * q2]     = pkh2(s[2 * kk + q2][0], s[2 * kk + q2][1]);
                ph[2 * q2 + 1] = pkh2(s[2 * kk + q2][2], s[2 * kk + q2][3]);
            }
#pragma unroll
            for (int blk = 0; blk < 2; blk++) {
                uint32_t vb[8][2];
#pragma unroll
                for (int p = 0; p < 4; p++)
                    ldsm4(&vb[2 * p][0], vbase + (blk * 64 + p * 16) * 144 + kk * 32);
#pragma unroll
                for (int j = 0; j < 8; j++) mma_f32a(o[blk * 8 + j], ph, vb[j]);
            }
        }
    }

    // ---- epilogue: y = O / l -> fp16 ----
    float i0 = 1.f / l0, i1 = 1.f / l1;
    size_t row0 = (size_t)b * Tn + qb * 128 + wid * 16 + lg;
#pragma unroll
    for (int nt = 0; nt < 16; nt++) {
        int col = h * 128 + nt * 8 + tq * 2;
        *(uint32_t*)(g_yh + row0 * Cn + col) =
            pkh2(o[nt][0] * i0, o[nt][1] * i0);
        *(uint32_t*)(g_yh + (row0 + 8) * Cn + col) =
            pkh2(o[nt][2] * i1, o[nt][3] * i1);
    }
}

// ---------------------------------------------------------------------------
extern "C" void kernel_launch(void* const* d_in, const int* in_sizes, int n_in,
                              void* d_out, int out_size) {
    const float* x      = (const float*)d_in[0];
    const float* cosb   = (const float*)d_in[1];
    const float* sinb   = (const float*)d_in[2];
    const float* w_attn = (const float*)d_in[3];
    const float* w_proj = (const float*)d_in[4];
    float* out = (float*)d_out;
    (void)in_sizes; (void)n_in; (void)out_size;

    (void)cudaFuncSetAttribute(hgemm1_kernel,
                               cudaFuncAttributeMaxDynamicSharedMemorySize, GSM);
    (void)cudaFuncSetAttribute(attn_kernel,
                               cudaFuncAttributeMaxDynamicSharedMemorySize, ATT_SMEM);

    float* qkvp = nullptr;
    f16 *xh, *wah, *wph, *yh;
    (void)cudaGetSymbolAddress((void**)&qkvp, g_qkv);
    (void)cudaGetSymbolAddress((void**)&xh, g_xh);
    (void)cudaGetSymbolAddress((void**)&wah, g_wah);
    (void)cudaGetSymbolAddress((void**)&wph, g_wph);
    (void)cudaGetSymbolAddress((void**)&yh, g_yh);

    // 0. fp16 conversions
    splitx_kernel<<<(ROWS * GK / 4) / 256, 256>>>(x);
    wsplit_kernel<<<dim3(QKVW / 32, GK / 32), dim3(32, 8)>>>(w_attn, wah, QKVW);
    wsplit_kernel<<<dim3(Cn / 32, GK / 32), dim3(32, 8)>>>(w_proj, wph, Cn);
    // 1. qkv = x @ w_attn (1-term fp16)
    hgemm1_kernel<<<dim3(QKVW / 128, ROWS / 64), 256, GSM>>>(xh, wah, qkvp, QKVW);
    // 2. RoPE -> q, k (fp16)
    rope_split_kernel<<<(ROWS * 4 * 5 * 64) / 256, 256>>>(cosb, sinb);
    // 3. v transpose (fp16)
    vsplit_kernel<<<dim3(Tn / 32, 4, 8), dim3(32, 8)>>>();
    // 4. attention -> yh
    attn_kernel<<<dim3(Tn / 128, 16, 2), 256, ATT_SMEM>>>();
    // 5. out = y @ w_proj (1-term fp16)
    hgemm1_kernel<<<dim3(Cn / 128, ROWS / 64), 256, GSM>>>(yh, wph, out, Cn);
}